// round 1
// baseline (speedup 1.0000x reference)
#include <cuda_runtime.h>
#include <cuda_fp16.h>
#include <mma.h>

using namespace nvcuda;

#define BATCH 65536
#define HDIM 128
#define NG 512     // 4*H gate width
#define MT 64      // batch rows per CTA
#define STEP_THREADS 256

// ---------------- device scratch (no allocs allowed) ----------------
__device__ __half g_Whh0e[NG * HDIM];      // enc layer0 recurrent weights, permuted
__device__ __half g_W1e[NG * 2 * HDIM];    // enc layer1 [Wih|Whh], permuted
__device__ __half g_Whh0d[NG * HDIM];      // dec layer0 recurrent
__device__ __half g_W1d[NG * 2 * HDIM];    // dec layer1 combined
__device__ float  g_Wx0e[NG * 7];          // enc layer0 input weights (fp32, tiny K)
__device__ float  g_Wx0d[NG * 2];          // dec layer0 input weights
__device__ float  g_b0e[NG], g_b1e[NG], g_b0d[NG], g_b1d[NG];

__device__ __half g_h0[BATCH * HDIM];
__device__ __half g_h1[BATCH * HDIM];
__device__ float  g_c0[BATCH * HDIM];
__device__ float  g_c1[BATCH * HDIM];
__device__ float  g_pred[BATCH * 2];

// ---------------- helpers ----------------
__device__ __forceinline__ float sigf(float x) {
    return __fdividef(1.0f, 1.0f + __expf(-x));
}
__device__ __forceinline__ float tanhfast(float x) {
    // tanh(x) = 2*sigmoid(2x) - 1
    return __fdividef(2.0f, 1.0f + __expf(-2.0f * x)) - 1.0f;
}

// ---------------- prep: permute weights into gate-interleaved layout ----------------
// n' = h*4 + gate  (gate order: i,f,g,o).  Row n' of permuted W = row gate*128+h of original.
__global__ void permute_weights(
    const float* __restrict__ eWih0, const float* __restrict__ eWhh0,
    const float* __restrict__ ebih0, const float* __restrict__ ebhh0,
    const float* __restrict__ eWih1, const float* __restrict__ eWhh1,
    const float* __restrict__ ebih1, const float* __restrict__ ebhh1,
    const float* __restrict__ dWih0, const float* __restrict__ dWhh0,
    const float* __restrict__ dbih0, const float* __restrict__ dbhh0,
    const float* __restrict__ dWih1, const float* __restrict__ dWhh1,
    const float* __restrict__ dbih1, const float* __restrict__ dbhh1)
{
    int np = blockIdx.x;          // 0..511
    int gate = np & 3;
    int h = np >> 2;
    int src = gate * 128 + h;

    for (int k = threadIdx.x; k < 128; k += blockDim.x) {
        g_Whh0e[np * 128 + k] = __float2half(eWhh0[src * 128 + k]);
        g_Whh0d[np * 128 + k] = __float2half(dWhh0[src * 128 + k]);
        g_W1e[np * 256 + k]       = __float2half(eWih1[src * 128 + k]);
        g_W1e[np * 256 + 128 + k] = __float2half(eWhh1[src * 128 + k]);
        g_W1d[np * 256 + k]       = __float2half(dWih1[src * 128 + k]);
        g_W1d[np * 256 + 128 + k] = __float2half(dWhh1[src * 128 + k]);
    }
    if (threadIdx.x < 7) g_Wx0e[np * 7 + threadIdx.x] = eWih0[src * 7 + threadIdx.x];
    if (threadIdx.x < 2) g_Wx0d[np * 2 + threadIdx.x] = dWih0[src * 2 + threadIdx.x];
    if (threadIdx.x == 0) {
        g_b0e[np] = ebih0[src] + ebhh0[src];
        g_b1e[np] = ebih1[src] + ebhh1[src];
        g_b0d[np] = dbih0[src] + dbhh0[src];
        g_b1d[np] = dbih1[src] + dbhh1[src];
    }
}

__global__ void init_states()
{
    long i = (long)blockIdx.x * blockDim.x + threadIdx.x;
    if (i < (long)BATCH * HDIM) {
        g_h0[i] = __float2half(0.0f);
        g_h1[i] = __float2half(0.0f);
        g_c0[i] = 0.0f;
        g_c1[i] = 0.0f;
    }
    if (i < (long)BATCH * 2) g_pred[i] = 0.0f;
}

// ---------------- fused LSTM step (GEMM + gating) ----------------
// SEL 0: enc layer0 (KG=128, XD=7, x from target)
// SEL 1: enc layer1 (KG=256)
// SEL 2: dec layer0 (KG=128, XD=2, x from g_pred)
// SEL 3: dec layer1 (KG=256)
template <int KG, int XD, int SEL>
__global__ __launch_bounds__(STEP_THREADS)
void lstm_step_kernel(const float* __restrict__ xsrc_target, int xoff)
{
    const __half* Wp;  const float* bias; const float* Wx;
    const __half* xh;  __half* hb;        float* cb;
    if constexpr (SEL == 0) { Wp = g_Whh0e; bias = g_b0e; Wx = g_Wx0e; xh = nullptr; hb = g_h0; cb = g_c0; }
    else if constexpr (SEL == 1) { Wp = g_W1e; bias = g_b1e; Wx = nullptr; xh = g_h0; hb = g_h1; cb = g_c1; }
    else if constexpr (SEL == 2) { Wp = g_Whh0d; bias = g_b0d; Wx = g_Wx0d; xh = nullptr; hb = g_h0; cb = g_c0; }
    else { Wp = g_W1d; bias = g_b1d; Wx = nullptr; xh = g_h0; hb = g_h1; cb = g_c1; }

    const float* xs = nullptr;
    int xstride = 0;
    if constexpr (SEL == 0) { xs = xsrc_target; xstride = 140; }  // target (B,20,7)
    if constexpr (SEL == 2) { xs = g_pred; xstride = 2; }

    extern __shared__ char smem[];
    __half* sA   = (__half*)smem;                               // MT*KG halves
    __half* sB   = (__half*)(smem + MT * KG * 2);               // NG*32 halves
    float*  sBias = (float*)(smem + MT * KG * 2 + NG * 32 * 2); // NG floats
    float*  sScr  = sBias + NG;                                 // 8 warps * 256
    float*  sX    = sScr + 8 * 256;                             // MT*XD
    float*  sWx   = sX + (XD > 0 ? MT * XD : 0);                // NG*XD

    int tid  = threadIdx.x;
    int warp = tid >> 5, lane = tid & 31;
    int wm = warp >> 2;   // 0..1  (32 rows each)
    int wn = warp & 3;    // 0..3  (128 gate-cols each)
    int m0 = blockIdx.x * MT;

    // ---- stage A = [x | h] (fp16) ----
    if (KG == 128) {
        for (int i = tid; i < MT * 16; i += STEP_THREADS) {
            int m = i >> 4, p = i & 15;
            ((uint4*)sA)[i] = ((const uint4*)(hb + (long)(m0 + m) * HDIM))[p];
        }
    } else {
        for (int i = tid; i < MT * 16; i += STEP_THREADS) {
            int m = i >> 4, p = i & 15;
            ((uint4*)sA)[m * 32 + p]      = ((const uint4*)(xh + (long)(m0 + m) * HDIM))[p];
            ((uint4*)sA)[m * 32 + 16 + p] = ((const uint4*)(hb + (long)(m0 + m) * HDIM))[p];
        }
    }
    for (int i = tid; i < NG; i += STEP_THREADS) sBias[i] = bias[i];
    if constexpr (XD > 0) {
        for (int i = tid; i < MT * XD; i += STEP_THREADS) {
            int m = i / XD, k = i - m * XD;
            sX[i] = xs[(long)(m0 + m) * xstride + xoff + k];
        }
        for (int i = tid; i < NG * XD; i += STEP_THREADS) sWx[i] = Wx[i];
    }
    __syncthreads();

    wmma::fragment<wmma::accumulator, 16, 16, 16, float> acc[2][8];
#pragma unroll
    for (int mi = 0; mi < 2; mi++)
#pragma unroll
        for (int nf = 0; nf < 8; nf++) wmma::fill_fragment(acc[mi][nf], 0.0f);

    // ---- K loop over 32-wide weight slabs staged in smem ----
#pragma unroll
    for (int ks = 0; ks < KG / 32; ks++) {
        for (int i = tid; i < NG * 4; i += STEP_THREADS) {     // 512 rows * 4 uint4 (32 halves)
            int n = i >> 2, p = i & 3;
            ((uint4*)sB)[i] = ((const uint4*)(Wp + (long)n * KG + ks * 32))[p];
        }
        __syncthreads();
#pragma unroll
        for (int kf = 0; kf < 2; kf++) {
            wmma::fragment<wmma::matrix_a, 16, 16, 16, __half, wmma::row_major> aF[2];
            wmma::load_matrix_sync(aF[0], sA + (wm * 32) * KG + ks * 32 + kf * 16, KG);
            wmma::load_matrix_sync(aF[1], sA + (wm * 32 + 16) * KG + ks * 32 + kf * 16, KG);
#pragma unroll
            for (int nf = 0; nf < 8; nf++) {
                wmma::fragment<wmma::matrix_b, 16, 16, 16, __half, wmma::col_major> bF;
                wmma::load_matrix_sync(bF, sB + (wn * 128 + nf * 16) * 32 + kf * 16, 32);
                wmma::mma_sync(acc[0][nf], aF[0], bF, acc[0][nf]);
                wmma::mma_sync(acc[1][nf], aF[1], bF, acc[1][nf]);
            }
        }
        __syncthreads();
    }

    // ---- epilogue: each 16x16 fragment holds all 4 gates for 4 hidden units ----
    float* scr = sScr + warp * 256;
#pragma unroll
    for (int mi = 0; mi < 2; mi++) {
#pragma unroll
        for (int nf = 0; nf < 8; nf++) {
            wmma::store_matrix_sync(scr, acc[mi][nf], 16, wmma::mem_row_major);
            __syncwarp();
#pragma unroll
            for (int pp = 0; pp < 2; pp++) {
                int p = lane + pp * 32;        // 0..63
                int r = p >> 2;                // row within fragment
                int hh = p & 3;                // hidden unit within fragment
                int mloc = wm * 32 + mi * 16 + r;
                long m = m0 + mloc;
                int np = wn * 128 + nf * 16 + hh * 4;   // n' of gate i
                int hidx = np >> 2;

                float pre0 = scr[r * 16 + hh * 4 + 0] + sBias[np + 0];
                float pre1 = scr[r * 16 + hh * 4 + 1] + sBias[np + 1];
                float pre2 = scr[r * 16 + hh * 4 + 2] + sBias[np + 2];
                float pre3 = scr[r * 16 + hh * 4 + 3] + sBias[np + 3];
                if constexpr (XD > 0) {
#pragma unroll
                    for (int k = 0; k < XD; k++) {
                        float xv = sX[mloc * XD + k];
                        pre0 += xv * sWx[(np + 0) * XD + k];
                        pre1 += xv * sWx[(np + 1) * XD + k];
                        pre2 += xv * sWx[(np + 2) * XD + k];
                        pre3 += xv * sWx[(np + 3) * XD + k];
                    }
                }
                float ig = sigf(pre0);
                float fg = sigf(pre1);
                float gg = tanhfast(pre2);
                float og = sigf(pre3);
                long ci = m * HDIM + hidx;
                float cc = fg * cb[ci] + ig * gg;
                cb[ci] = cc;
                hb[ci] = __float2half(og * tanhfast(cc));
            }
            __syncwarp();
        }
    }
}

// ---------------- output projection: pred = h1 @ out_W^T + out_b ----------------
__global__ void proj_kernel(const float* __restrict__ outW, const float* __restrict__ outb,
                            float* __restrict__ dout, int t)
{
    int warp = threadIdx.x >> 5, lane = threadIdx.x & 31;
    long m = (long)blockIdx.x * 8 + warp;
    const __half* hrow = g_h1 + m * HDIM;
    float a0 = 0.0f, a1 = 0.0f;
#pragma unroll
    for (int j = 0; j < 4; j++) {
        int k = lane + 32 * j;
        float hv = __half2float(hrow[k]);
        a0 += hv * __ldg(outW + k);
        a1 += hv * __ldg(outW + 128 + k);
    }
#pragma unroll
    for (int off = 16; off > 0; off >>= 1) {
        a0 += __shfl_down_sync(0xffffffffu, a0, off);
        a1 += __shfl_down_sync(0xffffffffu, a1, off);
    }
    if (lane == 0) {
        a0 += __ldg(outb);
        a1 += __ldg(outb + 1);
        dout[m * 50 + t * 2 + 0] = a0;
        dout[m * 50 + t * 2 + 1] = a1;
        g_pred[m * 2 + 0] = a0;
        g_pred[m * 2 + 1] = a1;
    }
}

// ---------------- host ----------------
static inline int smem_bytes(int KG, int XD)
{
    return MT * KG * 2 + NG * 32 * 2 + NG * 4 + 8 * 256 * 4 +
           (XD > 0 ? (MT * XD * 4 + NG * XD * 4) : 0);
}

extern "C" void kernel_launch(void* const* d_in, const int* in_sizes, int n_in,
                              void* d_out, int out_size)
{
    const float* target = (const float*)d_in[0];
    const float* eWih0 = (const float*)d_in[4];
    const float* eWhh0 = (const float*)d_in[5];
    const float* ebih0 = (const float*)d_in[6];
    const float* ebhh0 = (const float*)d_in[7];
    const float* eWih1 = (const float*)d_in[8];
    const float* eWhh1 = (const float*)d_in[9];
    const float* ebih1 = (const float*)d_in[10];
    const float* ebhh1 = (const float*)d_in[11];
    const float* dWih0 = (const float*)d_in[12];
    const float* dWhh0 = (const float*)d_in[13];
    const float* dbih0 = (const float*)d_in[14];
    const float* dbhh0 = (const float*)d_in[15];
    const float* dWih1 = (const float*)d_in[16];
    const float* dWhh1 = (const float*)d_in[17];
    const float* dbih1 = (const float*)d_in[18];
    const float* dbhh1 = (const float*)d_in[19];
    const float* outW  = (const float*)d_in[20];
    const float* outb  = (const float*)d_in[21];
    float* out = (float*)d_out;

    int smem_e0 = smem_bytes(128, 7);
    int smem_d0 = smem_bytes(128, 2);
    int smem_l1 = smem_bytes(256, 0);

    cudaFuncSetAttribute(lstm_step_kernel<128, 7, 0>, cudaFuncAttributeMaxDynamicSharedMemorySize, smem_e0);
    cudaFuncSetAttribute(lstm_step_kernel<256, 0, 1>, cudaFuncAttributeMaxDynamicSharedMemorySize, smem_l1);
    cudaFuncSetAttribute(lstm_step_kernel<128, 2, 2>, cudaFuncAttributeMaxDynamicSharedMemorySize, smem_d0);
    cudaFuncSetAttribute(lstm_step_kernel<256, 0, 3>, cudaFuncAttributeMaxDynamicSharedMemorySize, smem_l1);

    // prep
    permute_weights<<<NG, 128>>>(eWih0, eWhh0, ebih0, ebhh0,
                                 eWih1, eWhh1, ebih1, ebhh1,
                                 dWih0, dWhh0, dbih0, dbhh0,
                                 dWih1, dWhh1, dbih1, dbhh1);
    init_states<<<(BATCH * HDIM) / 256, 256>>>();

    const int grid = BATCH / MT;  // 1024

    // encoder: 20 steps, 2 layers
    for (int t = 0; t < 20; t++) {
        lstm_step_kernel<128, 7, 0><<<grid, STEP_THREADS, smem_e0>>>(target, t * 7);
        lstm_step_kernel<256, 0, 1><<<grid, STEP_THREADS, smem_l1>>>(nullptr, 0);
    }
    // decoder: 25 steps, 2 layers + projection
    for (int t = 0; t < 25; t++) {
        lstm_step_kernel<128, 2, 2><<<grid, STEP_THREADS, smem_d0>>>(nullptr, 0);
        lstm_step_kernel<256, 0, 3><<<grid, STEP_THREADS, smem_l1>>>(nullptr, 0);
        proj_kernel<<<BATCH / 8, 256>>>(outW, outb, out, t);
    }
}

// round 2
// speedup vs baseline: 1.4107x; 1.4107x over previous
#include <cuda_runtime.h>
#include <cuda_fp16.h>
#include <mma.h>

using namespace nvcuda;

#define BATCH 65536
#define HDIM 128
#define NG 512     // 4*H gate width
#define MT 64      // batch rows per CTA
#define STEP_THREADS 256
#define BLD 40     // padded B leading dim (halves): conflict-free LDSM

// ---------------- device scratch (no allocs allowed) ----------------
__device__ __half g_Whh0e[NG * HDIM];      // enc layer0 recurrent weights, permuted
__device__ __half g_W1e[NG * 2 * HDIM];    // enc layer1 [Wih|Whh], permuted
__device__ __half g_Whh0d[NG * HDIM];      // dec layer0 recurrent
__device__ __half g_W1d[NG * 2 * HDIM];    // dec layer1 combined
__device__ float  g_Wx0e[NG * 7];          // enc layer0 input weights (fp32, tiny K)
__device__ float  g_Wx0d[NG * 2];          // dec layer0 input weights
__device__ float  g_b0e[NG], g_b1e[NG], g_b0d[NG], g_b1d[NG];

__device__ __half g_h0[BATCH * HDIM];
__device__ __half g_h1[BATCH * HDIM];
__device__ float  g_c0[BATCH * HDIM];
__device__ float  g_c1[BATCH * HDIM];
__device__ float  g_pred[BATCH * 2];

// ---------------- helpers ----------------
__device__ __forceinline__ float sigf(float x) {
    return __fdividef(1.0f, 1.0f + __expf(-x));
}
__device__ __forceinline__ float tanhfast(float x) {
    return __fdividef(2.0f, 1.0f + __expf(-2.0f * x)) - 1.0f;
}

__device__ __forceinline__ unsigned smem_u32(const void* p) {
    return (unsigned)__cvta_generic_to_shared(p);
}
__device__ __forceinline__ void cp_async16(unsigned dst, const void* src) {
    asm volatile("cp.async.cg.shared.global [%0], [%1], 16;\n" :: "r"(dst), "l"(src));
}
__device__ __forceinline__ void cp_commit() {
    asm volatile("cp.async.commit_group;\n");
}
template <int N>
__device__ __forceinline__ void cp_wait() {
    asm volatile("cp.async.wait_group %0;\n" :: "n"(N));
}

// ---------------- prep: permute weights into gate-interleaved layout ----------------
// n' = h*4 + gate  (gate order: i,f,g,o).  Row n' of permuted W = row gate*128+h of original.
__global__ void permute_weights(
    const float* __restrict__ eWih0, const float* __restrict__ eWhh0,
    const float* __restrict__ ebih0, const float* __restrict__ ebhh0,
    const float* __restrict__ eWih1, const float* __restrict__ eWhh1,
    const float* __restrict__ ebih1, const float* __restrict__ ebhh1,
    const float* __restrict__ dWih0, const float* __restrict__ dWhh0,
    const float* __restrict__ dbih0, const float* __restrict__ dbhh0,
    const float* __restrict__ dWih1, const float* __restrict__ dWhh1,
    const float* __restrict__ dbih1, const float* __restrict__ dbhh1)
{
    int np = blockIdx.x;          // 0..511
    int gate = np & 3;
    int h = np >> 2;
    int src = gate * 128 + h;

    for (int k = threadIdx.x; k < 128; k += blockDim.x) {
        g_Whh0e[np * 128 + k] = __float2half(eWhh0[src * 128 + k]);
        g_Whh0d[np * 128 + k] = __float2half(dWhh0[src * 128 + k]);
        g_W1e[np * 256 + k]       = __float2half(eWih1[src * 128 + k]);
        g_W1e[np * 256 + 128 + k] = __float2half(eWhh1[src * 128 + k]);
        g_W1d[np * 256 + k]       = __float2half(dWih1[src * 128 + k]);
        g_W1d[np * 256 + 128 + k] = __float2half(dWhh1[src * 128 + k]);
    }
    if (threadIdx.x < 7) g_Wx0e[np * 7 + threadIdx.x] = eWih0[src * 7 + threadIdx.x];
    if (threadIdx.x < 2) g_Wx0d[np * 2 + threadIdx.x] = dWih0[src * 2 + threadIdx.x];
    if (threadIdx.x == 0) {
        g_b0e[np] = ebih0[src] + ebhh0[src];
        g_b1e[np] = ebih1[src] + ebhh1[src];
        g_b0d[np] = dbih0[src] + dbhh0[src];
        g_b1d[np] = dbih1[src] + dbhh1[src];
    }
}

__global__ void init_states()
{
    long i = (long)blockIdx.x * blockDim.x + threadIdx.x;
    if (i < (long)BATCH * HDIM) {
        g_h0[i] = __float2half(0.0f);
        g_h1[i] = __float2half(0.0f);
        g_c0[i] = 0.0f;
        g_c1[i] = 0.0f;
    }
    if (i < (long)BATCH * 2) g_pred[i] = 0.0f;
}

// ---------------- fused LSTM step (GEMM + gating) ----------------
// SEL 0: enc layer0 (KG=128, XD=7, x from target)
// SEL 1: enc layer1 (KG=256)
// SEL 2: dec layer0 (KG=128, XD=2, x from g_pred)
// SEL 3: dec layer1 (KG=256)
template <int KG, int XD, int SEL>
__global__ __launch_bounds__(STEP_THREADS)
void lstm_step_kernel(const float* __restrict__ xsrc_target, int xoff)
{
    constexpr int LDA = KG + 8;        // padded A leading dim (halves) — conflict-free
    constexpr int NS  = KG / 32;       // number of 32-wide K slabs
    constexpr int SLAB = NG * BLD;     // halves per B buffer

    const __half* Wp;  const float* bias; const float* Wx;
    const __half* xh;  __half* hb;        float* cb;
    if constexpr (SEL == 0) { Wp = g_Whh0e; bias = g_b0e; Wx = g_Wx0e; xh = nullptr; hb = g_h0; cb = g_c0; }
    else if constexpr (SEL == 1) { Wp = g_W1e; bias = g_b1e; Wx = nullptr; xh = g_h0; hb = g_h1; cb = g_c1; }
    else if constexpr (SEL == 2) { Wp = g_Whh0d; bias = g_b0d; Wx = g_Wx0d; xh = nullptr; hb = g_h0; cb = g_c0; }
    else { Wp = g_W1d; bias = g_b1d; Wx = nullptr; xh = g_h0; hb = g_h1; cb = g_c1; }

    const float* xs = nullptr;
    int xstride = 0;
    if constexpr (SEL == 0) { xs = xsrc_target; xstride = 140; }  // target (B,20,7)
    if constexpr (SEL == 2) { xs = g_pred; xstride = 2; }

    extern __shared__ char smem[];
    __half* sA    = (__half*)smem;                                   // MT*LDA halves
    __half* sB    = (__half*)(smem + MT * LDA * 2);                  // 2 * NG*BLD halves
    float*  sBias = (float*)(smem + MT * LDA * 2 + 2 * SLAB * 2);    // NG floats
    float*  sScr  = sBias + NG;                                      // 8 warps * 320 (16x20)
    float*  sX    = sScr + 8 * 320;                                  // MT*XD
    float*  sWx   = sX + (XD > 0 ? MT * XD : 0);                     // NG*XD

    int tid  = threadIdx.x;
    int warp = tid >> 5, lane = tid & 31;
    int wm = warp >> 2;   // 0..1  (32 rows each)
    int wn = warp & 3;    // 0..3  (128 gate-cols each)
    int m0 = blockIdx.x * MT;

    // ---- B slab prefetch helper (cp.async, 16B granules) ----
    auto issue_slab = [&](int ks, int buf) {
        __half* dst_base = sB + buf * SLAB;
        // 512 rows * 4 chunks of 16B each = 2048 cp.async / 256 threads = 8 per thread
        for (int i = tid; i < NG * 4; i += STEP_THREADS) {
            int n = i >> 2, p = i & 3;
            unsigned dst = smem_u32(dst_base + n * BLD + p * 8);
            cp_async16(dst, Wp + (long)n * KG + ks * 32 + p * 8);
        }
        cp_commit();
    };

    // kick off slab 0 ASAP
    issue_slab(0, 0);

    // ---- stage A = [x | h] (fp16) into padded layout ----
    if (KG == 128) {
        for (int i = tid; i < MT * 16; i += STEP_THREADS) {
            int m = i >> 4, p = i & 15;
            ((uint4*)(sA + m * LDA))[p] = ((const uint4*)(hb + (long)(m0 + m) * HDIM))[p];
        }
    } else {
        for (int i = tid; i < MT * 16; i += STEP_THREADS) {
            int m = i >> 4, p = i & 15;
            ((uint4*)(sA + m * LDA))[p]      = ((const uint4*)(xh + (long)(m0 + m) * HDIM))[p];
            ((uint4*)(sA + m * LDA))[16 + p] = ((const uint4*)(hb + (long)(m0 + m) * HDIM))[p];
        }
    }
    for (int i = tid; i < NG; i += STEP_THREADS) sBias[i] = bias[i];
    if constexpr (XD > 0) {
        for (int i = tid; i < MT * XD; i += STEP_THREADS) {
            int m = i / XD, k = i - m * XD;
            sX[i] = xs[(long)(m0 + m) * xstride + xoff + k];
        }
        for (int i = tid; i < NG * XD; i += STEP_THREADS) sWx[i] = Wx[i];
    }

    wmma::fragment<wmma::accumulator, 16, 16, 16, float> acc[2][8];
#pragma unroll
    for (int mi = 0; mi < 2; mi++)
#pragma unroll
        for (int nf = 0; nf < 8; nf++) wmma::fill_fragment(acc[mi][nf], 0.0f);

    // ---- K loop: double-buffered cp.async weight slabs ----
#pragma unroll
    for (int ks = 0; ks < NS; ks++) {
        if (ks + 1 < NS) {
            issue_slab(ks + 1, (ks + 1) & 1);
            cp_wait<1>();
        } else {
            cp_wait<0>();
        }
        __syncthreads();

        const __half* bbuf = sB + (ks & 1) * SLAB;
#pragma unroll
        for (int kf = 0; kf < 2; kf++) {
            wmma::fragment<wmma::matrix_a, 16, 16, 16, __half, wmma::row_major> aF[2];
            wmma::load_matrix_sync(aF[0], sA + (wm * 32) * LDA + ks * 32 + kf * 16, LDA);
            wmma::load_matrix_sync(aF[1], sA + (wm * 32 + 16) * LDA + ks * 32 + kf * 16, LDA);
#pragma unroll
            for (int nf = 0; nf < 8; nf++) {
                wmma::fragment<wmma::matrix_b, 16, 16, 16, __half, wmma::col_major> bF;
                wmma::load_matrix_sync(bF, bbuf + (wn * 128 + nf * 16) * BLD + kf * 16, BLD);
                wmma::mma_sync(acc[0][nf], aF[0], bF, acc[0][nf]);
                wmma::mma_sync(acc[1][nf], aF[1], bF, acc[1][nf]);
            }
        }
        __syncthreads();
    }

    // ---- epilogue: each 16x16 fragment holds all 4 gates for 4 hidden units ----
    float* scr = sScr + warp * 320;
#pragma unroll
    for (int mi = 0; mi < 2; mi++) {
#pragma unroll
        for (int nf = 0; nf < 8; nf++) {
            wmma::store_matrix_sync(scr, acc[mi][nf], 20, wmma::mem_row_major);
            __syncwarp();
#pragma unroll
            for (int pp = 0; pp < 2; pp++) {
                int p = lane + pp * 32;        // 0..63
                int r = p >> 2;                // row within fragment
                int hh = p & 3;                // hidden unit within fragment
                int mloc = wm * 32 + mi * 16 + r;
                long m = m0 + mloc;
                int np = wn * 128 + nf * 16 + hh * 4;   // n' of gate i
                int hidx = np >> 2;

                float pre0 = scr[r * 20 + hh * 4 + 0] + sBias[np + 0];
                float pre1 = scr[r * 20 + hh * 4 + 1] + sBias[np + 1];
                float pre2 = scr[r * 20 + hh * 4 + 2] + sBias[np + 2];
                float pre3 = scr[r * 20 + hh * 4 + 3] + sBias[np + 3];
                if constexpr (XD > 0) {
#pragma unroll
                    for (int k = 0; k < XD; k++) {
                        float xv = sX[mloc * XD + k];
                        pre0 += xv * sWx[(np + 0) * XD + k];
                        pre1 += xv * sWx[(np + 1) * XD + k];
                        pre2 += xv * sWx[(np + 2) * XD + k];
                        pre3 += xv * sWx[(np + 3) * XD + k];
                    }
                }
                float ig = sigf(pre0);
                float fg = sigf(pre1);
                float gg = tanhfast(pre2);
                float og = sigf(pre3);
                long ci = m * HDIM + hidx;
                float cc = fg * cb[ci] + ig * gg;
                cb[ci] = cc;
                hb[ci] = __float2half(og * tanhfast(cc));
            }
            __syncwarp();
        }
    }
}

// ---------------- output projection: pred = h1 @ out_W^T + out_b ----------------
__global__ void proj_kernel(const float* __restrict__ outW, const float* __restrict__ outb,
                            float* __restrict__ dout, int t)
{
    int warp = threadIdx.x >> 5, lane = threadIdx.x & 31;
    long m = (long)blockIdx.x * 8 + warp;
    const __half* hrow = g_h1 + m * HDIM;
    float a0 = 0.0f, a1 = 0.0f;
#pragma unroll
    for (int j = 0; j < 4; j++) {
        int k = lane + 32 * j;
        float hv = __half2float(hrow[k]);
        a0 += hv * __ldg(outW + k);
        a1 += hv * __ldg(outW + 128 + k);
    }
#pragma unroll
    for (int off = 16; off > 0; off >>= 1) {
        a0 += __shfl_down_sync(0xffffffffu, a0, off);
        a1 += __shfl_down_sync(0xffffffffu, a1, off);
    }
    if (lane == 0) {
        a0 += __ldg(outb);
        a1 += __ldg(outb + 1);
        dout[m * 50 + t * 2 + 0] = a0;
        dout[m * 50 + t * 2 + 1] = a1;
        g_pred[m * 2 + 0] = a0;
        g_pred[m * 2 + 1] = a1;
    }
}

// ---------------- host ----------------
static inline int smem_bytes(int KG, int XD)
{
    int lda = KG + 8;
    return MT * lda * 2 + 2 * NG * BLD * 2 + NG * 4 + 8 * 320 * 4 +
           (XD > 0 ? (MT * XD * 4 + NG * XD * 4) : 0);
}

extern "C" void kernel_launch(void* const* d_in, const int* in_sizes, int n_in,
                              void* d_out, int out_size)
{
    const float* target = (const float*)d_in[0];
    const float* eWih0 = (const float*)d_in[4];
    const float* eWhh0 = (const float*)d_in[5];
    const float* ebih0 = (const float*)d_in[6];
    const float* ebhh0 = (const float*)d_in[7];
    const float* eWih1 = (const float*)d_in[8];
    const float* eWhh1 = (const float*)d_in[9];
    const float* ebih1 = (const float*)d_in[10];
    const float* ebhh1 = (const float*)d_in[11];
    const float* dWih0 = (const float*)d_in[12];
    const float* dWhh0 = (const float*)d_in[13];
    const float* dbih0 = (const float*)d_in[14];
    const float* dbhh0 = (const float*)d_in[15];
    const float* dWih1 = (const float*)d_in[16];
    const float* dWhh1 = (const float*)d_in[17];
    const float* dbih1 = (const float*)d_in[18];
    const float* dbhh1 = (const float*)d_in[19];
    const float* outW  = (const float*)d_in[20];
    const float* outb  = (const float*)d_in[21];
    float* out = (float*)d_out;

    int smem_e0 = smem_bytes(128, 7);
    int smem_d0 = smem_bytes(128, 2);
    int smem_l1 = smem_bytes(256, 0);

    cudaFuncSetAttribute(lstm_step_kernel<128, 7, 0>, cudaFuncAttributeMaxDynamicSharedMemorySize, smem_e0);
    cudaFuncSetAttribute(lstm_step_kernel<256, 0, 1>, cudaFuncAttributeMaxDynamicSharedMemorySize, smem_l1);
    cudaFuncSetAttribute(lstm_step_kernel<128, 2, 2>, cudaFuncAttributeMaxDynamicSharedMemorySize, smem_d0);
    cudaFuncSetAttribute(lstm_step_kernel<256, 0, 3>, cudaFuncAttributeMaxDynamicSharedMemorySize, smem_l1);

    // prep
    permute_weights<<<NG, 128>>>(eWih0, eWhh0, ebih0, ebhh0,
                                 eWih1, eWhh1, ebih1, ebhh1,
                                 dWih0, dWhh0, dbih0, dbhh0,
                                 dWih1, dWhh1, dbih1, dbhh1);
    init_states<<<(BATCH * HDIM) / 256, 256>>>();

    const int grid = BATCH / MT;  // 1024

    // encoder: 20 steps, 2 layers
    for (int t = 0; t < 20; t++) {
        lstm_step_kernel<128, 7, 0><<<grid, STEP_THREADS, smem_e0>>>(target, t * 7);
        lstm_step_kernel<256, 0, 1><<<grid, STEP_THREADS, smem_l1>>>(nullptr, 0);
    }
    // decoder: 25 steps, 2 layers + projection
    for (int t = 0; t < 25; t++) {
        lstm_step_kernel<128, 2, 2><<<grid, STEP_THREADS, smem_d0>>>(nullptr, 0);
        lstm_step_kernel<256, 0, 3><<<grid, STEP_THREADS, smem_l1>>>(nullptr, 0);
        proj_kernel<<<BATCH / 8, 256>>>(outW, outb, out, t);
    }
}

// round 3
// speedup vs baseline: 2.1897x; 1.5522x over previous
#include <cuda_runtime.h>
#include <cuda_fp16.h>
#include <mma.h>

using namespace nvcuda;

#define BATCH 65536
#define HDIM 128
#define NG 512          // 4*H gate width
#define MT 64           // batch rows per CTA
#define LDA 264         // sH leading dim (halves): bank-conflict-free LDSM
#define LDC 132         // c leading dim (floats): conflict-free epilogue
#define BLD 40          // B slab leading dim (halves)
#define SLABSZ (NG * BLD)

// ---------------- device weights (permuted, no allocs allowed) ----------------
__device__ __half g_Whh0e[NG * HDIM];
__device__ __half g_W1e[NG * 2 * HDIM];
__device__ __half g_Whh0d[NG * HDIM];
__device__ __half g_W1d[NG * 2 * HDIM];
__device__ float  g_Wx0e[NG * 7];
__device__ float  g_Wx0d[NG * 2];
__device__ float  g_b0e[NG], g_b1e[NG], g_b0d[NG], g_b1d[NG];

// ---------------- helpers ----------------
__device__ __forceinline__ float sigf(float x) {
    return __fdividef(1.0f, 1.0f + __expf(-x));
}
__device__ __forceinline__ float tanhfast(float x) {
    return __fdividef(2.0f, 1.0f + __expf(-2.0f * x)) - 1.0f;
}
__device__ __forceinline__ unsigned smem_u32(const void* p) {
    return (unsigned)__cvta_generic_to_shared(p);
}
__device__ __forceinline__ void cp_async16(unsigned dst, const void* src) {
    asm volatile("cp.async.cg.shared.global [%0], [%1], 16;\n" :: "r"(dst), "l"(src));
}
__device__ __forceinline__ void cp_commit() {
    asm volatile("cp.async.commit_group;\n");
}
template <int N>
__device__ __forceinline__ void cp_wait() {
    asm volatile("cp.async.wait_group %0;\n" :: "n"(N));
}

// issue one 512x32 weight slab into buffer buf via cp.async (one group)
__device__ __forceinline__ void issue_slab(__half* sB, int tid,
                                           const __half* W, int KGw, int ks, int buf)
{
    __half* dst_base = sB + buf * SLABSZ;
    const __half* src = W + ks * 32;
#pragma unroll
    for (int r = 0; r < 8; r++) {
        int i = tid + r * 256;               // 2048 granules of 16B
        int n = i >> 2, p = i & 3;
        cp_async16(smem_u32(dst_base + n * BLD + p * 8), src + (long)n * KGw + p * 8);
    }
    cp_commit();
}

// ---------------- prep: permute weights into gate-interleaved layout ----------------
// n' = h*4 + gate (gate order i,f,g,o); row n' of permuted W = row gate*128+h of original.
__global__ void permute_weights(
    const float* __restrict__ eWih0, const float* __restrict__ eWhh0,
    const float* __restrict__ ebih0, const float* __restrict__ ebhh0,
    const float* __restrict__ eWih1, const float* __restrict__ eWhh1,
    const float* __restrict__ ebih1, const float* __restrict__ ebhh1,
    const float* __restrict__ dWih0, const float* __restrict__ dWhh0,
    const float* __restrict__ dbih0, const float* __restrict__ dbhh0,
    const float* __restrict__ dWih1, const float* __restrict__ dWhh1,
    const float* __restrict__ dbih1, const float* __restrict__ dbhh1)
{
    int np = blockIdx.x;
    int gate = np & 3;
    int h = np >> 2;
    int src = gate * 128 + h;

    for (int k = threadIdx.x; k < 128; k += blockDim.x) {
        g_Whh0e[np * 128 + k] = __float2half(eWhh0[src * 128 + k]);
        g_Whh0d[np * 128 + k] = __float2half(dWhh0[src * 128 + k]);
        g_W1e[np * 256 + k]       = __float2half(eWih1[src * 128 + k]);
        g_W1e[np * 256 + 128 + k] = __float2half(eWhh1[src * 128 + k]);
        g_W1d[np * 256 + k]       = __float2half(dWih1[src * 128 + k]);
        g_W1d[np * 256 + 128 + k] = __float2half(dWhh1[src * 128 + k]);
    }
    if (threadIdx.x < 7) g_Wx0e[np * 7 + threadIdx.x] = eWih0[src * 7 + threadIdx.x];
    if (threadIdx.x < 2) g_Wx0d[np * 2 + threadIdx.x] = dWih0[src * 2 + threadIdx.x];
    if (threadIdx.x == 0) {
        g_b0e[np] = ebih0[src] + ebhh0[src];
        g_b1e[np] = ebih1[src] + ebhh1[src];
        g_b0d[np] = dbih0[src] + dbhh0[src];
        g_b1d[np] = dbih1[src] + dbhh1[src];
    }
}

// ---------------- one LSTM layer step, fully smem-resident ----------------
// A = sH cols [0, KG) (row-major, ldm=LDA). Gates -> update sC, write h to sH col hOff.
// Prefetches next phase's slab0 (nextW) during the last MMA iteration.
template <int KG, int XD>
__device__ __forceinline__ void layer_body(
    int tid, int lane, int wm, int wn, int warp,
    __half* sH, __half* sB, float* sC, const float* bias, float* sScr,
    const float* sWx, float* sX, const float* xg, int xstride,
    const __half* Wp, const __half* nextW, int nextKG, int hOff)
{
    constexpr int NS = KG / 32;

    // stage external x (encoder) into sX; decoder passes xg=nullptr (sX=sPred already)
    if (XD > 0 && xg != nullptr) {
#pragma unroll
        for (int r = 0; r < 2; r++) {
            int i = tid + r * 256;
            if (i < MT * XD) {
                int m = i / XD, k = i - m * XD;
                sX[i] = xg[(long)m * xstride + k];
            }
        }
    }

    wmma::fragment<wmma::accumulator, 16, 16, 16, float> acc[2][8];
#pragma unroll
    for (int mi = 0; mi < 2; mi++)
#pragma unroll
        for (int nf = 0; nf < 8; nf++) wmma::fill_fragment(acc[mi][nf], 0.0f);

#pragma unroll
    for (int ks = 0; ks < NS; ks++) {
        if (ks + 1 < NS) issue_slab(sB, tid, Wp, KG, ks + 1, (ks + 1) & 1);
        else             issue_slab(sB, tid, nextW, nextKG, 0, 0);   // cross-phase prefetch
        cp_wait<1>();
        __syncthreads();

        const __half* bb = sB + (ks & 1) * SLABSZ;
#pragma unroll
        for (int kf = 0; kf < 2; kf++) {
            wmma::fragment<wmma::matrix_a, 16, 16, 16, __half, wmma::row_major> aF[2];
            wmma::load_matrix_sync(aF[0], sH + (wm * 32) * LDA + ks * 32 + kf * 16, LDA);
            wmma::load_matrix_sync(aF[1], sH + (wm * 32 + 16) * LDA + ks * 32 + kf * 16, LDA);
#pragma unroll
            for (int nf = 0; nf < 8; nf++) {
                wmma::fragment<wmma::matrix_b, 16, 16, 16, __half, wmma::col_major> bF;
                wmma::load_matrix_sync(bF, bb + (wn * 128 + nf * 16) * BLD + kf * 16, BLD);
                wmma::mma_sync(acc[0][nf], aF[0], bF, acc[0][nf]);
                wmma::mma_sync(acc[1][nf], aF[1], bF, acc[1][nf]);
            }
        }
        __syncthreads();
    }

    // epilogue: each 16x16 fragment holds all 4 gates for 4 hidden units
    float* scr = sScr + warp * 320;
#pragma unroll
    for (int mi = 0; mi < 2; mi++) {
#pragma unroll
        for (int nf = 0; nf < 8; nf++) {
            wmma::store_matrix_sync(scr, acc[mi][nf], 20, wmma::mem_row_major);
            __syncwarp();
#pragma unroll
            for (int pp = 0; pp < 2; pp++) {
                int p = lane + pp * 32;
                int r = p >> 2;
                int hh = p & 3;
                int mloc = wm * 32 + mi * 16 + r;
                int np = wn * 128 + nf * 16 + hh * 4;
                int hidx = np >> 2;

                float pre0 = scr[r * 20 + hh * 4 + 0] + bias[np + 0];
                float pre1 = scr[r * 20 + hh * 4 + 1] + bias[np + 1];
                float pre2 = scr[r * 20 + hh * 4 + 2] + bias[np + 2];
                float pre3 = scr[r * 20 + hh * 4 + 3] + bias[np + 3];
                if constexpr (XD > 0) {
#pragma unroll
                    for (int k = 0; k < XD; k++) {
                        float xv = sX[mloc * XD + k];
                        pre0 += xv * sWx[(np + 0) * XD + k];
                        pre1 += xv * sWx[(np + 1) * XD + k];
                        pre2 += xv * sWx[(np + 2) * XD + k];
                        pre3 += xv * sWx[(np + 3) * XD + k];
                    }
                }
                float ig = sigf(pre0);
                float fg = sigf(pre1);
                float gg = tanhfast(pre2);
                float og = sigf(pre3);
                float cc = fg * sC[mloc * LDC + hidx] + ig * gg;
                sC[mloc * LDC + hidx] = cc;
                sH[mloc * LDA + hOff + hidx] = __float2half(og * tanhfast(cc));
            }
            __syncwarp();
        }
    }
}

// ---------------- the fused full-network kernel ----------------
__global__ __launch_bounds__(256)
void lstm_fused(const float* __restrict__ target,
                const float* __restrict__ outW, const float* __restrict__ outb,
                float* __restrict__ dout)
{
    extern __shared__ char smem[];
    __half* sH    = (__half*)smem;                                  // 64 x 264  (h0|h1|pad)
    __half* sB    = (__half*)(smem + 33792);                        // 2 x 512 x 40
    float*  sC0   = (float*)(smem + 115712);                        // 64 x 132
    float*  sC1   = (float*)(smem + 149504);                        // 64 x 132
    float*  sBias = (float*)(smem + 183296);                        // 4 x 512
    float*  sScr  = (float*)(smem + 191488);                        // 8 x 320
    float*  sWxE  = (float*)(smem + 201728);                        // 512 x 7
    float*  sWxD  = (float*)(smem + 216064);                        // 512 x 2
    float*  sX    = (float*)(smem + 220160);                        // 64 x 7
    float*  sPred = (float*)(smem + 221952);                        // 64 x 2
    float*  sOW   = (float*)(smem + 222464);                        // 2 x 128
    float*  sOB   = (float*)(smem + 223488);                        // 2

    int tid  = threadIdx.x;
    int warp = tid >> 5, lane = tid & 31;
    int wm = warp >> 2, wn = warp & 3;
    long m0 = (long)blockIdx.x * MT;

    // ---- init smem state ----
    for (int i = tid; i < MT * LDA; i += 256) sH[i] = __float2half(0.0f);
    for (int i = tid; i < MT * LDC; i += 256) { sC0[i] = 0.0f; sC1[i] = 0.0f; }
    for (int i = tid; i < NG; i += 256) {
        sBias[i]            = g_b0e[i];
        sBias[NG + i]       = g_b1e[i];
        sBias[2 * NG + i]   = g_b0d[i];
        sBias[3 * NG + i]   = g_b1d[i];
    }
    for (int i = tid; i < NG * 7; i += 256) sWxE[i] = g_Wx0e[i];
    for (int i = tid; i < NG * 2; i += 256) sWxD[i] = g_Wx0d[i];
    if (tid < 256) sOW[tid] = outW[tid];
    if (tid < 2) sOB[tid] = outb[tid];
    if (tid < 128) sPred[tid] = 0.0f;

    issue_slab(sB, tid, g_Whh0e, 128, 0, 0);   // first slab of first phase
    __syncthreads();

    // ---- encoder: 20 steps x 2 layers ----
    for (int t = 0; t < 20; t++) {
        layer_body<128, 7>(tid, lane, wm, wn, warp, sH, sB, sC0, sBias, sScr,
                           sWxE, sX, target + m0 * 140 + t * 7, 140,
                           g_Whh0e, g_W1e, 256, 0);
        const __half* nW = (t < 19) ? g_Whh0e : g_Whh0d;
        layer_body<256, 0>(tid, lane, wm, wn, warp, sH, sB, sC1, sBias + NG, sScr,
                           nullptr, nullptr, nullptr, 0,
                           g_W1e, nW, 128, 128);
    }

    // ---- decoder: 25 steps x 2 layers + projection ----
    for (int t = 0; t < 25; t++) {
        layer_body<128, 2>(tid, lane, wm, wn, warp, sH, sB, sC0, sBias + 2 * NG, sScr,
                           sWxD, sPred, nullptr, 2,
                           g_Whh0d, g_W1d, 256, 0);
        const __half* nW = (t < 24) ? g_Whh0d : g_W1d;   // last one is a harmless dummy
        layer_body<256, 0>(tid, lane, wm, wn, warp, sH, sB, sC1, sBias + 3 * NG, sScr,
                           nullptr, nullptr, nullptr, 0,
                           g_W1d, nW, 128, 128);
        __syncthreads();   // h1 complete before projection reads it

        // projection: pred = h1 @ outW^T + outb   (8 warps x 8 rows)
#pragma unroll
        for (int r8 = 0; r8 < 8; r8++) {
            int mloc = warp * 8 + r8;
            float a0 = 0.0f, a1 = 0.0f;
#pragma unroll
            for (int j = 0; j < 4; j++) {
                int k = lane + 32 * j;
                float hv = __half2float(sH[mloc * LDA + 128 + k]);
                a0 += hv * sOW[k];
                a1 += hv * sOW[128 + k];
            }
#pragma unroll
            for (int off = 16; off > 0; off >>= 1) {
                a0 += __shfl_down_sync(0xffffffffu, a0, off);
                a1 += __shfl_down_sync(0xffffffffu, a1, off);
            }
            if (lane == 0) {
                a0 += sOB[0];
                a1 += sOB[1];
                long m = m0 + mloc;
                dout[m * 50 + t * 2 + 0] = a0;
                dout[m * 50 + t * 2 + 1] = a1;
                sPred[mloc * 2 + 0] = a0;
                sPred[mloc * 2 + 1] = a1;
            }
        }
        // next layer0's internal syncthreads orders sPred writes before its epilogue reads
    }
    cp_wait<0>();   // drain trailing dummy prefetch
}

// ---------------- host ----------------
#define FUSED_SMEM 223496

extern "C" void kernel_launch(void* const* d_in, const int* in_sizes, int n_in,
                              void* d_out, int out_size)
{
    const float* target = (const float*)d_in[0];
    const float* eWih0 = (const float*)d_in[4];
    const float* eWhh0 = (const float*)d_in[5];
    const float* ebih0 = (const float*)d_in[6];
    const float* ebhh0 = (const float*)d_in[7];
    const float* eWih1 = (const float*)d_in[8];
    const float* eWhh1 = (const float*)d_in[9];
    const float* ebih1 = (const float*)d_in[10];
    const float* ebhh1 = (const float*)d_in[11];
    const float* dWih0 = (const float*)d_in[12];
    const float* dWhh0 = (const float*)d_in[13];
    const float* dbih0 = (const float*)d_in[14];
    const float* dbhh0 = (const float*)d_in[15];
    const float* dWih1 = (const float*)d_in[16];
    const float* dWhh1 = (const float*)d_in[17];
    const float* dbih1 = (const float*)d_in[18];
    const float* dbhh1 = (const float*)d_in[19];
    const float* outW  = (const float*)d_in[20];
    const float* outb  = (const float*)d_in[21];
    float* out = (float*)d_out;

    cudaFuncSetAttribute(lstm_fused, cudaFuncAttributeMaxDynamicSharedMemorySize, FUSED_SMEM);

    permute_weights<<<NG, 128>>>(eWih0, eWhh0, ebih0, ebhh0,
                                 eWih1, eWhh1, ebih1, ebhh1,
                                 dWih0, dWhh0, dbih0, dbhh0,
                                 dWih1, dWhh1, dbih1, dbhh1);

    lstm_fused<<<BATCH / MT, 256, FUSED_SMEM>>>(target, outW, outb, out);
}

// round 4
// speedup vs baseline: 2.8360x; 1.2952x over previous
#include <cuda_runtime.h>
#include <cuda_fp16.h>

#define BATCH 65536
#define HDIM 128
#define NG 512
#define MT 64
#define LDA 296          // sH leading dim (halves): conflict-free LDSM (word stride ≡ 20 mod 32)
#define LDC 130          // c leading dim (floats): conflict-free epilogue
#define BLD 40           // B slab leading dim (halves)
#define SLABSZ (NG * BLD)

// ---------------- device weights (permuted + K-padded, no allocs) ----------------
__device__ __half g_W0e[NG * 160];   // [Whh | Wx(7) | 0] enc layer0, K=160
__device__ __half g_W0d[NG * 160];   // [Whh | Wx(2) | 0] dec layer0, K=160
__device__ __half g_W1e[NG * 256];   // [Wih | Whh]       enc layer1, K=256
__device__ __half g_W1d[NG * 256];   // [Wih | Whh]       dec layer1, K=256
__device__ float  g_bias[4 * NG];    // phase 0..3 combined biases

// ---------------- helpers ----------------
__device__ __forceinline__ float sigf(float x) {
    return __fdividef(1.0f, 1.0f + __expf(-x));
}
__device__ __forceinline__ float tanha(float x) {
    float y;
    asm("tanh.approx.f32 %0, %1;" : "=f"(y) : "f"(x));
    return y;
}
__device__ __forceinline__ unsigned smem_u32(const void* p) {
    return (unsigned)__cvta_generic_to_shared(p);
}
__device__ __forceinline__ void cp_async16(unsigned dst, const void* src) {
    asm volatile("cp.async.cg.shared.global [%0], [%1], 16;\n" :: "r"(dst), "l"(src));
}
__device__ __forceinline__ void cp_commit() {
    asm volatile("cp.async.commit_group;\n");
}
template <int N>
__device__ __forceinline__ void cp_wait() {
    asm volatile("cp.async.wait_group %0;\n" :: "n"(N));
}
__device__ __forceinline__ void ldsm4(unsigned addr, unsigned& r0, unsigned& r1,
                                      unsigned& r2, unsigned& r3) {
    asm volatile("ldmatrix.sync.aligned.m8n8.x4.shared.b16 {%0,%1,%2,%3}, [%4];"
                 : "=r"(r0), "=r"(r1), "=r"(r2), "=r"(r3) : "r"(addr));
}
__device__ __forceinline__ void mma16816(float* d, const unsigned* a, unsigned b0, unsigned b1) {
    asm volatile(
        "mma.sync.aligned.m16n8k16.row.col.f32.f16.f16.f32 "
        "{%0,%1,%2,%3},{%4,%5,%6,%7},{%8,%9},{%0,%1,%2,%3};"
        : "+f"(d[0]), "+f"(d[1]), "+f"(d[2]), "+f"(d[3])
        : "r"(a[0]), "r"(a[1]), "r"(a[2]), "r"(a[3]), "r"(b0), "r"(b1));
}

// issue one 512x32 weight slab into buffer buf via cp.async (one commit group)
__device__ __forceinline__ void issue_slab(__half* sB, int tid,
                                           const __half* W, int KGw, int ks, int buf)
{
    __half* dst_base = sB + buf * SLABSZ;
    const __half* src = W + ks * 32;
#pragma unroll
    for (int r = 0; r < 8; r++) {
        int i = tid + r * 256;
        int n = i >> 2, p = i & 3;
        cp_async16(smem_u32(dst_base + n * BLD + p * 8), src + (long)n * KGw + p * 8);
    }
    cp_commit();
}

// ---------------- prep: gate-interleaved permutation + K padding ----------------
// n' = h*4 + gate (order i,f,g,o); row n' = row gate*128+h of original.
__global__ void permute_weights(
    const float* __restrict__ eWih0, const float* __restrict__ eWhh0,
    const float* __restrict__ ebih0, const float* __restrict__ ebhh0,
    const float* __restrict__ eWih1, const float* __restrict__ eWhh1,
    const float* __restrict__ ebih1, const float* __restrict__ ebhh1,
    const float* __restrict__ dWih0, const float* __restrict__ dWhh0,
    const float* __restrict__ dbih0, const float* __restrict__ dbhh0,
    const float* __restrict__ dWih1, const float* __restrict__ dWhh1,
    const float* __restrict__ dbih1, const float* __restrict__ dbhh1)
{
    int np = blockIdx.x;
    int gate = np & 3;
    int h = np >> 2;
    int src = gate * 128 + h;

    for (int k = threadIdx.x; k < 128; k += blockDim.x) {
        g_W0e[np * 160 + k] = __float2half(eWhh0[src * 128 + k]);
        g_W0d[np * 160 + k] = __float2half(dWhh0[src * 128 + k]);
        g_W1e[np * 256 + k]       = __float2half(eWih1[src * 128 + k]);
        g_W1e[np * 256 + 128 + k] = __float2half(eWhh1[src * 128 + k]);
        g_W1d[np * 256 + k]       = __float2half(dWih1[src * 128 + k]);
        g_W1d[np * 256 + 128 + k] = __float2half(dWhh1[src * 128 + k]);
    }
    for (int k = threadIdx.x; k < 32; k += blockDim.x) {
        g_W0e[np * 160 + 128 + k] = (k < 7) ? __float2half(eWih0[src * 7 + k]) : __float2half(0.0f);
        g_W0d[np * 160 + 128 + k] = (k < 2) ? __float2half(dWih0[src * 2 + k]) : __float2half(0.0f);
    }
    if (threadIdx.x == 0) {
        g_bias[0 * NG + np] = ebih0[src] + ebhh0[src];
        g_bias[1 * NG + np] = ebih1[src] + ebhh1[src];
        g_bias[2 * NG + np] = dbih0[src] + dbhh0[src];
        g_bias[3 * NG + np] = dbih1[src] + dbhh1[src];
    }
}

// ---------------- one LSTM layer step (raw mma + register epilogue) ----------------
// A rows: sH; layer0 (KG=160): cols 0..159 (h0 | x | 0); layer1 (KG=256): cols 0..127 (h0)
// and 160..287 (h1) — slab k>=4 shifted by +32. Writes h to sH col hOff, updates sC.
template <int KG>
__device__ __forceinline__ void layer(
    int tid, int lane, int wm, int wn,
    __half* sH, __half* sB, float* sC, const float* bias,
    const __half* Wp, const __half* nextW, int nextKG,
    int hOff, int buf0)
{
    constexpr int NS = KG / 32;

    // accumulators initialized with bias (broadcast across rows)
    float acc[2][16][4];
#pragma unroll
    for (int ni = 0; ni < 16; ni++) {
        int c0 = wn * 128 + ni * 8 + 2 * (lane & 3);
        float b0 = bias[c0], b1 = bias[c0 + 1];
#pragma unroll
        for (int mi = 0; mi < 2; mi++) {
            acc[mi][ni][0] = b0; acc[mi][ni][1] = b1;
            acc[mi][ni][2] = b0; acc[mi][ni][3] = b1;
        }
    }

#pragma unroll
    for (int ks = 0; ks < NS; ks++) {
        if (ks + 1 < NS) issue_slab(sB, tid, Wp, KG, ks + 1, (buf0 + ks + 1) & 1);
        else             issue_slab(sB, tid, nextW, nextKG, 0, (buf0 + NS) & 1);
        cp_wait<1>();
        __syncthreads();

        int acol = ks * 32;
        if (KG == 256 && ks >= 4) acol += 32;   // h1 lives at cols 160..287
        const __half* bb = sB + ((buf0 + ks) & 1) * SLABSZ;

#pragma unroll
        for (int kf = 0; kf < 2; kf++) {
            unsigned a[2][4];
#pragma unroll
            for (int mi = 0; mi < 2; mi++) {
                unsigned addr = smem_u32(sH + (wm * 32 + mi * 16 + (lane & 15)) * LDA
                                            + acol + kf * 16 + (lane >> 4) * 8);
                ldsm4(addr, a[mi][0], a[mi][1], a[mi][2], a[mi][3]);
            }
#pragma unroll
            for (int nq = 0; nq < 8; nq++) {
                unsigned b0, b1, b2, b3;
                unsigned baddr = smem_u32(bb + (wn * 128 + nq * 16 + (lane & 15)) * BLD
                                             + kf * 16 + (lane >> 4) * 8);
                ldsm4(baddr, b0, b1, b2, b3);
#pragma unroll
                for (int mi = 0; mi < 2; mi++) {
                    mma16816(acc[mi][2 * nq],     a[mi], b0, b2);
                    mma16816(acc[mi][2 * nq + 1], a[mi], b1, b3);
                }
            }
        }
        __syncthreads();
    }

    // register epilogue: lane pair exchange gathers all 4 gates per (row, hidden)
    int odd = lane & 1;
#pragma unroll
    for (int mi = 0; mi < 2; mi++) {
#pragma unroll
        for (int ni = 0; ni < 16; ni++) {
            float* d = acc[mi][ni];
            float e1 = __shfl_xor_sync(0xffffffffu, odd ? d[0] : d[2], 1);
            float e2 = __shfl_xor_sync(0xffffffffu, odd ? d[1] : d[3], 1);
            float pi = odd ? e1 : d[0];
            float pf = odd ? e2 : d[1];
            float pg = odd ? d[2] : e1;
            float po = odd ? d[3] : e2;
            int mloc = wm * 32 + mi * 16 + (lane >> 2) + 8 * odd;
            int hidx = wn * 32 + ni * 2 + ((lane >> 1) & 1);
            float cc = sigf(pf) * sC[mloc * LDC + hidx] + sigf(pi) * tanha(pg);
            sC[mloc * LDC + hidx] = cc;
            sH[mloc * LDA + hOff + hidx] = __float2half(sigf(po) * tanha(cc));
        }
    }
}

// ---------------- the fused full-network kernel ----------------
__global__ __launch_bounds__(256, 1)
void lstm_fused(const float* __restrict__ target,
                const float* __restrict__ outW, const float* __restrict__ outb,
                float* __restrict__ dout)
{
    extern __shared__ char smem[];
    __half* sH    = (__half*)smem;                  // 64 x 296:  h0 | x/pred/0 | h1
    __half* sB    = (__half*)(smem + 37888);        // 2 x 512 x 40
    float*  sC0   = (float*)(smem + 119808);        // 64 x 130
    float*  sC1   = (float*)(smem + 153088);        // 64 x 130
    float*  sBias = (float*)(smem + 186368);        // 4 x 512
    float*  sOW   = (float*)(smem + 194560);        // 2 x 128
    float*  sOB   = (float*)(smem + 195584);        // 2

    int tid  = threadIdx.x;
    int warp = tid >> 5, lane = tid & 31;
    int wm = warp >> 2, wn = warp & 3;
    long m0 = (long)blockIdx.x * MT;

    // ---- init ----
    for (int i = tid; i < MT * LDA; i += 256) sH[i] = __float2half(0.0f);
    for (int i = tid; i < MT * LDC; i += 256) { sC0[i] = 0.0f; sC1[i] = 0.0f; }
    for (int i = tid; i < 4 * NG; i += 256) sBias[i] = g_bias[i];
    if (tid < 256) sOW[tid] = outW[tid];
    if (tid < 2) sOB[tid] = outb[tid];

    issue_slab(sB, tid, g_W0e, 160, 0, 0);
    __syncthreads();

    int par = 0;
    // ---- encoder ----
    for (int t = 0; t < 20; t++) {
        for (int i = tid; i < MT * 7; i += 256) {   // stage x -> sH cols 128..134
            int m = i / 7, k = i - m * 7;
            sH[m * LDA + 128 + k] = __float2half(target[(m0 + m) * 140 + t * 7 + k]);
        }
        layer<160>(tid, lane, wm, wn, sH, sB, sC0, sBias,
                   g_W0e, g_W1e, 256, 0, par);
        layer<256>(tid, lane, wm, wn, sH, sB, sC1, sBias + NG,
                   g_W1e, (t < 19) ? g_W0e : g_W0d, 160, 160, par ^ 1);
        par ^= 1;
    }

    // zero pred input for first decoder step (cols 130..134 residue hits zero weights)
    for (int i = tid; i < MT * 2; i += 256) {
        int m = i >> 1, k = i & 1;
        sH[m * LDA + 128 + k] = __float2half(0.0f);
    }

    // ---- decoder ----
    for (int t = 0; t < 25; t++) {
        layer<160>(tid, lane, wm, wn, sH, sB, sC0, sBias + 2 * NG,
                   g_W0d, g_W1d, 256, 0, par);
        layer<256>(tid, lane, wm, wn, sH, sB, sC1, sBias + 3 * NG,
                   g_W1d, g_W0d, 160, 160, par ^ 1);
        par ^= 1;
        __syncthreads();   // h1 complete before projection

        // projection: pred = h1 @ outW^T + outb
#pragma unroll
        for (int r8 = 0; r8 < 8; r8++) {
            int mloc = warp * 8 + r8;
            float a0 = 0.0f, a1 = 0.0f;
#pragma unroll
            for (int j = 0; j < 4; j++) {
                int k = lane + 32 * j;
                float hv = __half2float(sH[mloc * LDA + 160 + k]);
                a0 += hv * sOW[k];
                a1 += hv * sOW[128 + k];
            }
#pragma unroll
            for (int off = 16; off > 0; off >>= 1) {
                a0 += __shfl_down_sync(0xffffffffu, a0, off);
                a1 += __shfl_down_sync(0xffffffffu, a1, off);
            }
            if (lane == 0) {
                a0 += sOB[0];
                a1 += sOB[1];
                long m = m0 + mloc;
                dout[m * 50 + t * 2 + 0] = a0;
                dout[m * 50 + t * 2 + 1] = a1;
                sH[mloc * LDA + 128] = __float2half(a0);
                sH[mloc * LDA + 129] = __float2half(a1);
            }
        }
    }
    cp_wait<0>();
    __syncthreads();
}

// ---------------- host ----------------
#define FUSED_SMEM 195592

extern "C" void kernel_launch(void* const* d_in, const int* in_sizes, int n_in,
                              void* d_out, int out_size)
{
    const float* target = (const float*)d_in[0];
    const float* eWih0 = (const float*)d_in[4];
    const float* eWhh0 = (const float*)d_in[5];
    const float* ebih0 = (const float*)d_in[6];
    const float* ebhh0 = (const float*)d_in[7];
    const float* eWih1 = (const float*)d_in[8];
    const float* eWhh1 = (const float*)d_in[9];
    const float* ebih1 = (const float*)d_in[10];
    const float* ebhh1 = (const float*)d_in[11];
    const float* dWih0 = (const float*)d_in[12];
    const float* dWhh0 = (const float*)d_in[13];
    const float* dbih0 = (const float*)d_in[14];
    const float* dbhh0 = (const float*)d_in[15];
    const float* dWih1 = (const float*)d_in[16];
    const float* dWhh1 = (const float*)d_in[17];
    const float* dbih1 = (const float*)d_in[18];
    const float* dbhh1 = (const float*)d_in[19];
    const float* outW  = (const float*)d_in[20];
    const float* outb  = (const float*)d_in[21];
    float* out = (float*)d_out;

    cudaFuncSetAttribute(lstm_fused, cudaFuncAttributeMaxDynamicSharedMemorySize, FUSED_SMEM);

    permute_weights<<<NG, 128>>>(eWih0, eWhh0, ebih0, ebhh0,
                                 eWih1, eWhh1, ebih1, ebhh1,
                                 dWih0, dWhh0, dbih0, dbhh0,
                                 dWih1, dWhh1, dbih1, dbhh1);

    lstm_fused<<<BATCH / MT, 256, FUSED_SMEM>>>(target, outW, outb, out);
}

// round 5
// speedup vs baseline: 3.0592x; 1.0787x over previous
#include <cuda_runtime.h>
#include <cuda_fp16.h>

#define BATCH 65536
#define HDIM 128
#define NG 512
#define MT 64
#define LDA 296          // sH leading dim (halves): conflict-free LDSM
#define LDC 130          // c leading dim (floats): conflict-free epilogue
#define BLD 40           // B slab leading dim (halves)
#define SLABSZ (NG * BLD)
#define NT 512           // threads per CTA (16 warps)

// ---------------- device weights (permuted + K-padded, no allocs) ----------------
__device__ __half g_W0e[NG * 160];   // [Whh | Wx(7) | 0] enc layer0, K=160
__device__ __half g_W0d[NG * 160];   // [Whh | Wx(2) | 0] dec layer0, K=160
__device__ __half g_W1e[NG * 256];   // [Wih | Whh]       enc layer1, K=256
__device__ __half g_W1d[NG * 256];   // [Wih | Whh]       dec layer1, K=256
__device__ float  g_bias[4 * NG];

// ---------------- helpers ----------------
__device__ __forceinline__ float sigf(float x) {
    return __fdividef(1.0f, 1.0f + __expf(-x));
}
__device__ __forceinline__ float tanha(float x) {
    float y;
    asm("tanh.approx.f32 %0, %1;" : "=f"(y) : "f"(x));
    return y;
}
__device__ __forceinline__ unsigned smem_u32(const void* p) {
    return (unsigned)__cvta_generic_to_shared(p);
}
__device__ __forceinline__ void cp_async16(unsigned dst, const void* src) {
    asm volatile("cp.async.cg.shared.global [%0], [%1], 16;\n" :: "r"(dst), "l"(src));
}
__device__ __forceinline__ void cp_commit() {
    asm volatile("cp.async.commit_group;\n");
}
template <int N>
__device__ __forceinline__ void cp_wait() {
    asm volatile("cp.async.wait_group %0;\n" :: "n"(N));
}
__device__ __forceinline__ void ldsm4(unsigned addr, unsigned& r0, unsigned& r1,
                                      unsigned& r2, unsigned& r3) {
    asm volatile("ldmatrix.sync.aligned.m8n8.x4.shared.b16 {%0,%1,%2,%3}, [%4];"
                 : "=r"(r0), "=r"(r1), "=r"(r2), "=r"(r3) : "r"(addr));
}
__device__ __forceinline__ void mma16816(float* d, const unsigned* a, unsigned b0, unsigned b1) {
    asm volatile(
        "mma.sync.aligned.m16n8k16.row.col.f32.f16.f16.f32 "
        "{%0,%1,%2,%3},{%4,%5,%6,%7},{%8,%9},{%0,%1,%2,%3};"
        : "+f"(d[0]), "+f"(d[1]), "+f"(d[2]), "+f"(d[3])
        : "r"(a[0]), "r"(a[1]), "r"(a[2]), "r"(a[3]), "r"(b0), "r"(b1));
}

// issue one 512x32 weight slab into buffer buf via cp.async (one commit group)
__device__ __forceinline__ void issue_slab(__half* sB, int tid,
                                           const __half* W, int KGw, int ks, int buf)
{
    __half* dst_base = sB + buf * SLABSZ;
    const __half* src = W + ks * 32;
#pragma unroll
    for (int r = 0; r < 4; r++) {
        int i = tid + r * NT;                // 2048 granules of 16B
        int n = i >> 2, p = i & 3;
        cp_async16(smem_u32(dst_base + n * BLD + p * 8), src + (long)n * KGw + p * 8);
    }
    cp_commit();
}

// ---------------- prep: gate-interleaved permutation + K padding ----------------
__global__ void permute_weights(
    const float* __restrict__ eWih0, const float* __restrict__ eWhh0,
    const float* __restrict__ ebih0, const float* __restrict__ ebhh0,
    const float* __restrict__ eWih1, const float* __restrict__ eWhh1,
    const float* __restrict__ ebih1, const float* __restrict__ ebhh1,
    const float* __restrict__ dWih0, const float* __restrict__ dWhh0,
    const float* __restrict__ dbih0, const float* __restrict__ dbhh0,
    const float* __restrict__ dWih1, const float* __restrict__ dWhh1,
    const float* __restrict__ dbih1, const float* __restrict__ dbhh1)
{
    int np = blockIdx.x;
    int gate = np & 3;
    int h = np >> 2;
    int src = gate * 128 + h;

    for (int k = threadIdx.x; k < 128; k += blockDim.x) {
        g_W0e[np * 160 + k] = __float2half(eWhh0[src * 128 + k]);
        g_W0d[np * 160 + k] = __float2half(dWhh0[src * 128 + k]);
        g_W1e[np * 256 + k]       = __float2half(eWih1[src * 128 + k]);
        g_W1e[np * 256 + 128 + k] = __float2half(eWhh1[src * 128 + k]);
        g_W1d[np * 256 + k]       = __float2half(dWih1[src * 128 + k]);
        g_W1d[np * 256 + 128 + k] = __float2half(dWhh1[src * 128 + k]);
    }
    for (int k = threadIdx.x; k < 32; k += blockDim.x) {
        g_W0e[np * 160 + 128 + k] = (k < 7) ? __float2half(eWih0[src * 7 + k]) : __float2half(0.0f);
        g_W0d[np * 160 + 128 + k] = (k < 2) ? __float2half(dWih0[src * 2 + k]) : __float2half(0.0f);
    }
    if (threadIdx.x == 0) {
        g_bias[0 * NG + np] = ebih0[src] + ebhh0[src];
        g_bias[1 * NG + np] = ebih1[src] + ebhh1[src];
        g_bias[2 * NG + np] = dbih0[src] + dbhh0[src];
        g_bias[3 * NG + np] = dbih1[src] + dbhh1[src];
    }
}

// ---------------- one LSTM layer step (raw mma + register epilogue) ----------------
// 16 warps: wm in {0,1} (32 rows), wn in {0..7} (64 gate-cols). Warp tile 32x64.
// Single __syncthreads per slab: wait -> sync -> issue next -> MMA.
template <int KG>
__device__ __forceinline__ void layer(
    int tid, int lane, int wm, int wn,
    __half* sH, __half* sB, float* sC, const float* bias,
    const __half* Wp, const __half* nextW, int nextKG,
    int hOff, int buf0)
{
    constexpr int NS = KG / 32;

    float acc[2][8][4];
#pragma unroll
    for (int ni = 0; ni < 8; ni++) {
        int c0 = wn * 64 + ni * 8 + 2 * (lane & 3);
        float b0 = bias[c0], b1 = bias[c0 + 1];
#pragma unroll
        for (int mi = 0; mi < 2; mi++) {
            acc[mi][ni][0] = b0; acc[mi][ni][1] = b1;
            acc[mi][ni][2] = b0; acc[mi][ni][3] = b1;
        }
    }

#pragma unroll
    for (int ks = 0; ks < NS; ks++) {
        cp_wait<0>();
        __syncthreads();   // slab ks visible; all prior reads of the buffer being re-filled done
        if (ks + 1 < NS) issue_slab(sB, tid, Wp, KG, ks + 1, (buf0 + ks + 1) & 1);
        else             issue_slab(sB, tid, nextW, nextKG, 0, (buf0 + NS) & 1);

        int acol = ks * 32;
        if (KG == 256 && ks >= 4) acol += 32;   // h1 lives at cols 160..287
        const __half* bb = sB + ((buf0 + ks) & 1) * SLABSZ;

#pragma unroll
        for (int kf = 0; kf < 2; kf++) {
            unsigned a[2][4];
#pragma unroll
            for (int mi = 0; mi < 2; mi++) {
                unsigned addr = smem_u32(sH + (wm * 32 + mi * 16 + (lane & 15)) * LDA
                                            + acol + kf * 16 + (lane >> 4) * 8);
                ldsm4(addr, a[mi][0], a[mi][1], a[mi][2], a[mi][3]);
            }
#pragma unroll
            for (int nq = 0; nq < 4; nq++) {
                unsigned b0, b1, b2, b3;
                unsigned baddr = smem_u32(bb + (wn * 64 + nq * 16 + (lane & 15)) * BLD
                                             + kf * 16 + (lane >> 4) * 8);
                ldsm4(baddr, b0, b1, b2, b3);
#pragma unroll
                for (int mi = 0; mi < 2; mi++) {
                    mma16816(acc[mi][2 * nq],     a[mi], b0, b2);
                    mma16816(acc[mi][2 * nq + 1], a[mi], b1, b3);
                }
            }
        }
    }
    __syncthreads();   // all MMA reads of sH done before epilogue rewrites h

    // register epilogue: lane-pair exchange gathers all 4 gates per (row, hidden)
    int odd = lane & 1;
#pragma unroll
    for (int mi = 0; mi < 2; mi++) {
#pragma unroll
        for (int ni = 0; ni < 8; ni++) {
            float* d = acc[mi][ni];
            float e1 = __shfl_xor_sync(0xffffffffu, odd ? d[0] : d[2], 1);
            float e2 = __shfl_xor_sync(0xffffffffu, odd ? d[1] : d[3], 1);
            float pi = odd ? e1 : d[0];
            float pf = odd ? e2 : d[1];
            float pg = odd ? d[2] : e1;
            float po = odd ? d[3] : e2;
            int mloc = wm * 32 + mi * 16 + (lane >> 2) + 8 * odd;
            int hidx = wn * 16 + ni * 2 + ((lane >> 1) & 1);
            float cc = sigf(pf) * sC[mloc * LDC + hidx] + sigf(pi) * tanha(pg);
            sC[mloc * LDC + hidx] = cc;
            sH[mloc * LDA + hOff + hidx] = __float2half(sigf(po) * tanha(cc));
        }
    }
}

// ---------------- the fused full-network kernel ----------------
__global__ __launch_bounds__(NT, 1)
void lstm_fused(const float* __restrict__ target,
                const float* __restrict__ outW, const float* __restrict__ outb,
                float* __restrict__ dout)
{
    extern __shared__ char smem[];
    __half* sH    = (__half*)smem;                  // 64 x 296:  h0 | x/pred/0 | h1
    __half* sB    = (__half*)(smem + 37888);        // 2 x 512 x 40
    float*  sC0   = (float*)(smem + 119808);        // 64 x 130
    float*  sC1   = (float*)(smem + 153088);        // 64 x 130
    float*  sBias = (float*)(smem + 186368);        // 4 x 512
    float*  sOW   = (float*)(smem + 194560);        // 2 x 128
    float*  sOB   = (float*)(smem + 195584);        // 2

    int tid  = threadIdx.x;
    int warp = tid >> 5, lane = tid & 31;
    int wm = warp >> 3, wn = warp & 7;
    long m0 = (long)blockIdx.x * MT;

    // ---- init ----
    for (int i = tid; i < MT * LDA; i += NT) sH[i] = __float2half(0.0f);
    for (int i = tid; i < MT * LDC; i += NT) { sC0[i] = 0.0f; sC1[i] = 0.0f; }
    for (int i = tid; i < 4 * NG; i += NT) sBias[i] = g_bias[i];
    if (tid < 256) sOW[tid] = outW[tid];
    if (tid < 2) sOB[tid] = outb[tid];

    issue_slab(sB, tid, g_W0e, 160, 0, 0);
    __syncthreads();

    int par = 0;
    // ---- encoder ----
    for (int t = 0; t < 20; t++) {
        for (int i = tid; i < MT * 7; i += NT) {    // stage x -> sH cols 128..134
            int m = i / 7, k = i - m * 7;
            sH[m * LDA + 128 + k] = __float2half(target[(m0 + m) * 140 + t * 7 + k]);
        }
        layer<160>(tid, lane, wm, wn, sH, sB, sC0, sBias,
                   g_W0e, g_W1e, 256, 0, par);
        layer<256>(tid, lane, wm, wn, sH, sB, sC1, sBias + NG,
                   g_W1e, (t < 19) ? g_W0e : g_W0d, 160, 160, par ^ 1);
        par ^= 1;
    }

    // zero pred input for first decoder step (cols 130..134 residue hits zero weights)
    for (int i = tid; i < MT * 2; i += NT) {
        int m = i >> 1, k = i & 1;
        sH[m * LDA + 128 + k] = __float2half(0.0f);
    }

    // ---- decoder ----
    for (int t = 0; t < 25; t++) {
        layer<160>(tid, lane, wm, wn, sH, sB, sC0, sBias + 2 * NG,
                   g_W0d, g_W1d, 256, 0, par);
        layer<256>(tid, lane, wm, wn, sH, sB, sC1, sBias + 3 * NG,
                   g_W1d, g_W0d, 160, 160, par ^ 1);
        par ^= 1;
        __syncthreads();   // h1 complete before projection

        // projection: pred = h1 @ outW^T + outb   (16 warps x 4 rows)
#pragma unroll
        for (int r4 = 0; r4 < 4; r4++) {
            int mloc = warp * 4 + r4;
            float a0 = 0.0f, a1 = 0.0f;
#pragma unroll
            for (int j = 0; j < 4; j++) {
                int k = lane + 32 * j;
                float hv = __half2float(sH[mloc * LDA + 160 + k]);
                a0 += hv * sOW[k];
                a1 += hv * sOW[128 + k];
            }
#pragma unroll
            for (int off = 16; off > 0; off >>= 1) {
                a0 += __shfl_down_sync(0xffffffffu, a0, off);
                a1 += __shfl_down_sync(0xffffffffu, a1, off);
            }
            if (lane == 0) {
                a0 += sOB[0];
                a1 += sOB[1];
                long m = m0 + mloc;
                dout[m * 50 + t * 2 + 0] = a0;
                dout[m * 50 + t * 2 + 1] = a1;
                sH[mloc * LDA + 128] = __float2half(a0);
                sH[mloc * LDA + 129] = __float2half(a1);
            }
        }
    }
    cp_wait<0>();
    __syncthreads();
}

// ---------------- host ----------------
#define FUSED_SMEM 195592

extern "C" void kernel_launch(void* const* d_in, const int* in_sizes, int n_in,
                              void* d_out, int out_size)
{
    const float* target = (const float*)d_in[0];
    const float* eWih0 = (const float*)d_in[4];
    const float* eWhh0 = (const float*)d_in[5];
    const float* ebih0 = (const float*)d_in[6];
    const float* ebhh0 = (const float*)d_in[7];
    const float* eWih1 = (const float*)d_in[8];
    const float* eWhh1 = (const float*)d_in[9];
    const float* ebih1 = (const float*)d_in[10];
    const float* ebhh1 = (const float*)d_in[11];
    const float* dWih0 = (const float*)d_in[12];
    const float* dWhh0 = (const float*)d_in[13];
    const float* dbih0 = (const float*)d_in[14];
    const float* dbhh0 = (const float*)d_in[15];
    const float* dWih1 = (const float*)d_in[16];
    const float* dWhh1 = (const float*)d_in[17];
    const float* dbih1 = (const float*)d_in[18];
    const float* dbhh1 = (const float*)d_in[19];
    const float* outW  = (const float*)d_in[20];
    const float* outb  = (const float*)d_in[21];
    float* out = (float*)d_out;

    cudaFuncSetAttribute(lstm_fused, cudaFuncAttributeMaxDynamicSharedMemorySize, FUSED_SMEM);

    permute_weights<<<NG, 128>>>(eWih0, eWhh0, ebih0, ebhh0,
                                 eWih1, eWhh1, ebih1, ebhh1,
                                 dWih0, dWhh0, dbih0, dbhh0,
                                 dWih1, dWhh1, dbih1, dbhh1);

    lstm_fused<<<BATCH / MT, NT, FUSED_SMEM>>>(target, outW, outb, out);
}

// round 7
// speedup vs baseline: 3.9555x; 1.2930x over previous
#include <cuda_runtime.h>
#include <cuda_fp16.h>
#include <cstdint>

#define BATCH 65536
#define HDIM 128
#define NG 512
#define MT 64
#define LDA 296          // sH leading dim (halves): conflict-free LDSM
#define LDC 130          // c leading dim (floats): conflict-free epilogue
#define BLD 40           // B slab leading dim (halves)
#define SLABP (NG * BLD) // halves per padded slab (20480)
#define SLABB (SLABP * 2)// bytes per slab (40960)
#define NT 512           // threads per CTA (16 warps)

// ---- padded, pre-swizzled weight slabs in gmem (flat smem image) ----
// layout: [e0: 5 slabs][e1: 8][d0: 5][d1: 8]  (26 total)
__device__ __align__(16) __half g_S[26 * SLABP];
__device__ float g_bias[4 * NG];

#define OFF_E0 0
#define OFF_E1 (5 * SLABP)
#define OFF_D0 (13 * SLABP)
#define OFF_D1 (18 * SLABP)

// ---------------- helpers ----------------
__device__ __forceinline__ float tanha(float x) {
    float y; asm("tanh.approx.f32 %0, %1;" : "=f"(y) : "f"(x)); return y;
}
__device__ __forceinline__ float sigf(float x) {          // 1 MUFU sigmoid
    return fmaf(0.5f, tanha(0.5f * x), 0.5f);
}
__device__ __forceinline__ unsigned smem_u32(const void* p) {
    return (unsigned)__cvta_generic_to_shared(p);
}
__device__ __forceinline__ void mbar_init(uint32_t a, uint32_t c) {
    asm volatile("mbarrier.init.shared.b64 [%0], %1;" :: "r"(a), "r"(c) : "memory");
}
__device__ __forceinline__ void mbar_inval(uint32_t a) {
    asm volatile("mbarrier.inval.shared.b64 [%0];" :: "r"(a) : "memory");
}
__device__ __forceinline__ void mbar_expect_tx(uint32_t a, uint32_t bytes) {
    asm volatile("mbarrier.arrive.expect_tx.shared.b64 _, [%0], %1;"
                 :: "r"(a), "r"(bytes) : "memory");
}
__device__ __forceinline__ void mbar_wait(uint32_t mbar, int parity) {
    uint32_t done;
    asm volatile(
        "{\n\t.reg .pred p;\n\t"
        "mbarrier.try_wait.parity.acquire.cta.shared::cta.b64 p, [%1], %2;\n\t"
        "selp.b32 %0, 1, 0, p;\n\t}"
        : "=r"(done) : "r"(mbar), "r"((uint32_t)parity) : "memory");
    if (!done) {
        asm volatile(
            "{\n\t.reg .pred P1;\n\t"
            "WAIT_LOOP_%=:\n\t"
            "mbarrier.try_wait.parity.acquire.cta.shared::cta.b64 P1, [%0], %1, 0x989680;\n\t"
            "@P1 bra.uni WAIT_DONE_%=;\n\t"
            "bra.uni WAIT_LOOP_%=;\n\t"
            "WAIT_DONE_%=:\n\t}"
            :: "r"(mbar), "r"((uint32_t)parity) : "memory");
    }
}
__device__ __forceinline__ void bulk_g2s(uint32_t dst, const void* src,
                                         uint32_t bytes, uint32_t mbar) {
    asm volatile(
        "cp.async.bulk.shared::cta.global.mbarrier::complete_tx::bytes [%0], [%1], %2, [%3];"
        :: "r"(dst), "l"(src), "r"(bytes), "r"(mbar) : "memory");
}
__device__ __forceinline__ void ldsm4(unsigned addr, unsigned& r0, unsigned& r1,
                                      unsigned& r2, unsigned& r3) {
    asm volatile("ldmatrix.sync.aligned.m8n8.x4.shared.b16 {%0,%1,%2,%3}, [%4];"
                 : "=r"(r0), "=r"(r1), "=r"(r2), "=r"(r3) : "r"(addr));
}
__device__ __forceinline__ void mma16816(float* d, const unsigned* a, unsigned b0, unsigned b1) {
    asm volatile(
        "mma.sync.aligned.m16n8k16.row.col.f32.f16.f16.f32 "
        "{%0,%1,%2,%3},{%4,%5,%6,%7},{%8,%9},{%0,%1,%2,%3};"
        : "+f"(d[0]), "+f"(d[1]), "+f"(d[2]), "+f"(d[3])
        : "r"(a[0]), "r"(a[1]), "r"(a[2]), "r"(a[3]), "r"(b0), "r"(b1));
}

// ---------------- prep: gate-interleave + K-fold into padded slab images ----------------
// n' = h*4 + gate (order i,f,g,o); row n' = row gate*128+h of original.
__global__ void build_weights(
    const float* __restrict__ eWih0, const float* __restrict__ eWhh0,
    const float* __restrict__ ebih0, const float* __restrict__ ebhh0,
    const float* __restrict__ eWih1, const float* __restrict__ eWhh1,
    const float* __restrict__ ebih1, const float* __restrict__ ebhh1,
    const float* __restrict__ dWih0, const float* __restrict__ dWhh0,
    const float* __restrict__ dbih0, const float* __restrict__ dbhh0,
    const float* __restrict__ dWih1, const float* __restrict__ dWhh1,
    const float* __restrict__ dbih1, const float* __restrict__ dbhh1)
{
    int sb = blockIdx.x;        // 0..25
    int phase, ks;
    if (sb < 5)       { phase = 0; ks = sb; }
    else if (sb < 13) { phase = 1; ks = sb - 5; }
    else if (sb < 18) { phase = 2; ks = sb - 13; }
    else              { phase = 3; ks = sb - 18; }
    __half* dst = g_S + (long)sb * SLABP;

    int np = threadIdx.x;       // 0..511
    int gate = np & 3, h = np >> 2;
    int src = gate * 128 + h;

    for (int c = 0; c < BLD; c++) {
        float v = 0.0f;
        if (c < 32) {
            int kglob = ks * 32 + c;
            if (phase == 0) {
                if (kglob < 128) v = eWhh0[src * 128 + kglob];
                else if (kglob < 135) v = eWih0[src * 7 + (kglob - 128)];
            } else if (phase == 1) {
                v = (kglob < 128) ? eWih1[src * 128 + kglob] : eWhh1[src * 128 + kglob - 128];
            } else if (phase == 2) {
                if (kglob < 128) v = dWhh0[src * 128 + kglob];
                else if (kglob < 130) v = dWih0[src * 2 + (kglob - 128)];
            } else {
                v = (kglob < 128) ? dWih1[src * 128 + kglob] : dWhh1[src * 128 + kglob - 128];
            }
        }
        dst[np * BLD + c] = __float2half(v);
    }
    if (ks == 0) {
        const float* bi = (phase == 0) ? ebih0 : (phase == 1) ? ebih1 : (phase == 2) ? dbih0 : dbih1;
        const float* bh = (phase == 0) ? ebhh0 : (phase == 1) ? ebhh1 : (phase == 2) ? dbhh0 : dbhh1;
        g_bias[phase * NG + np] = bi[src] + bh[src];
    }
}

// ---- smem offsets (bytes) ----
#define SMO_H    0          // 64 x 296 fp16          (37888)
#define SMO_B    37888      // 2 x 20480 fp16 slabs   (81920)
#define SMO_C0   119808     // 64 x 130 fp32          (33280)
#define SMO_C1   153088     // 64 x 130 fp32          (33280)
#define SMO_BIAS 186368     // 4 x 512 fp32           (8192)
#define SMO_OW   194560     // 256 fp32               (1024)
#define SMO_OB   195584     // 2 fp32
#define SMO_MB   195600     // 2 mbarriers (16B aligned)
#define SMEM_TOTAL 195616

// ---------------- one LSTM layer step (raw mma, bulk-copy weight pipeline) ----------------
// A rows: sH; layer0 (KG=160): cols 0..159 (h0|x|0); layer1 (KG=256): h0 at 0..127,
// h1 at 160..287 (slab ks>=4 shifted +32). Writes h to sH col hOff, updates sC.
template <int KG>
__device__ __forceinline__ void layer(
    int tid, int lane, int wm, int wn, uint32_t smem_base,
    __half* sH, __half* sB, float* sC, const float* bias,
    const __half* Wp, const __half* nextW,
    int hOff, int& sc, int (&ph)[2])
{
    constexpr int NS = KG / 32;
    const uint32_t mb0 = smem_base + SMO_MB;

    float acc[2][8][4];
#pragma unroll
    for (int ni = 0; ni < 8; ni++) {
        int c0 = wn * 64 + ni * 8 + 2 * (lane & 3);
        float b0 = bias[c0], b1 = bias[c0 + 1];
#pragma unroll
        for (int mi = 0; mi < 2; mi++) {
            acc[mi][ni][0] = b0; acc[mi][ni][1] = b1;
            acc[mi][ni][2] = b0; acc[mi][ni][3] = b1;
        }
    }

#pragma unroll
    for (int ks = 0; ks < NS; ks++) {
        __syncthreads();   // reuse guard: all reads of the buffer being refilled are done
        if (tid == 0) {
            const __half* nsrc = (ks + 1 < NS) ? (Wp + (long)(ks + 1) * SLABP) : nextW;
            if (nsrc) {
                int nb = (sc + 1) & 1;
                mbar_expect_tx(mb0 + nb * 8, SLABB);
                bulk_g2s(smem_base + SMO_B + nb * SLABB, nsrc, SLABB, mb0 + nb * 8);
            }
        }
        int cb = sc & 1;
        mbar_wait(mb0 + cb * 8, ph[cb]);
        ph[cb] ^= 1;

        int acol = ks * 32;
        if (KG == 256 && ks >= 4) acol += 32;   // h1 lives at cols 160..287
        const __half* bb = sB + cb * SLABP;

#pragma unroll
        for (int kf = 0; kf < 2; kf++) {
            unsigned a[2][4];
#pragma unroll
            for (int mi = 0; mi < 2; mi++) {
                unsigned addr = smem_u32(sH + (wm * 32 + mi * 16 + (lane & 15)) * LDA
                                            + acol + kf * 16 + (lane >> 4) * 8);
                ldsm4(addr, a[mi][0], a[mi][1], a[mi][2], a[mi][3]);
            }
#pragma unroll
            for (int nq = 0; nq < 4; nq++) {
                unsigned b0, b1, b2, b3;
                unsigned baddr = smem_u32(bb + (wn * 64 + nq * 16 + (lane & 15)) * BLD
                                             + kf * 16 + (lane >> 4) * 8);
                ldsm4(baddr, b0, b1, b2, b3);
#pragma unroll
                for (int mi = 0; mi < 2; mi++) {
                    mma16816(acc[mi][2 * nq],     a[mi], b0, b2);
                    mma16816(acc[mi][2 * nq + 1], a[mi], b1, b3);
                }
            }
        }
        sc++;
    }
    __syncthreads();   // all MMA reads of sH done before epilogue rewrites h

    // register epilogue: lane-pair exchange gathers all 4 gates per (row, hidden)
    int odd = lane & 1;
#pragma unroll
    for (int mi = 0; mi < 2; mi++) {
#pragma unroll
        for (int ni = 0; ni < 8; ni++) {
            float* d = acc[mi][ni];
            float e1 = __shfl_xor_sync(0xffffffffu, odd ? d[0] : d[2], 1);
            float e2 = __shfl_xor_sync(0xffffffffu, odd ? d[1] : d[3], 1);
            float pi = odd ? e1 : d[0];
            float pf = odd ? e2 : d[1];
            float pg = odd ? d[2] : e1;
            float po = odd ? d[3] : e2;
            int mloc = wm * 32 + mi * 16 + (lane >> 2) + 8 * odd;
            int hidx = wn * 16 + ni * 2 + ((lane >> 1) & 1);
            float cc = sigf(pf) * sC[mloc * LDC + hidx] + sigf(pi) * tanha(pg);
            sC[mloc * LDC + hidx] = cc;
            sH[mloc * LDA + hOff + hidx] = __float2half(sigf(po) * tanha(cc));
        }
    }
}

// ---------------- the fused full-network kernel ----------------
__global__ __launch_bounds__(NT, 1)
void lstm_fused(const float* __restrict__ target,
                const float* __restrict__ outW, const float* __restrict__ outb,
                float* __restrict__ dout)
{
    extern __shared__ char smem[];
    uint32_t smem_base = smem_u32(smem);
    __half* sH    = (__half*)(smem + SMO_H);
    __half* sB    = (__half*)(smem + SMO_B);
    float*  sC0   = (float*)(smem + SMO_C0);
    float*  sC1   = (float*)(smem + SMO_C1);
    float*  sBias = (float*)(smem + SMO_BIAS);
    float*  sOW   = (float*)(smem + SMO_OW);
    float*  sOB   = (float*)(smem + SMO_OB);

    int tid  = threadIdx.x;
    int warp = tid >> 5, lane = tid & 31;
    int wm = warp >> 3, wn = warp & 7;
    long m0 = (long)blockIdx.x * MT;

    // ---- init ----
    if (tid == 0) {
        mbar_init(smem_base + SMO_MB, 1);
        mbar_init(smem_base + SMO_MB + 8, 1);
    }
    for (int i = tid; i < MT * LDA; i += NT) sH[i] = __float2half(0.0f);
    for (int i = tid; i < MT * LDC; i += NT) { sC0[i] = 0.0f; sC1[i] = 0.0f; }
    for (int i = tid; i < 4 * NG; i += NT) sBias[i] = g_bias[i];
    if (tid < 256) sOW[tid] = outW[tid];
    if (tid < 2) sOB[tid] = outb[tid];
    __syncthreads();

    // kick off first slab (enc layer0 slab 0 -> buffer 0)
    if (tid == 0) {
        mbar_expect_tx(smem_base + SMO_MB, SLABB);
        bulk_g2s(smem_base + SMO_B, g_S + OFF_E0, SLABB, smem_base + SMO_MB);
    }

    int sc = 0;
    int ph[2] = {0, 0};

    // ---- encoder ----
    for (int t = 0; t < 20; t++) {
        for (int i = tid; i < MT * 7; i += NT) {    // stage x -> sH cols 128..134
            int m = i / 7, k = i - m * 7;
            sH[m * LDA + 128 + k] = __float2half(target[(m0 + m) * 140 + t * 7 + k]);
        }
        layer<160>(tid, lane, wm, wn, smem_base, sH, sB, sC0, sBias,
                   g_S + OFF_E0, g_S + OFF_E1, 0, sc, ph);
        layer<256>(tid, lane, wm, wn, smem_base, sH, sB, sC1, sBias + NG,
                   g_S + OFF_E1, (t < 19) ? g_S + OFF_E0 : g_S + OFF_D0, 160, sc, ph);
    }

    // zero pred input for first decoder step (cols 130..134 residue hits zero weights)
    for (int i = tid; i < MT * 2; i += NT) {
        int m = i >> 1, k = i & 1;
        sH[m * LDA + 128 + k] = __float2half(0.0f);
    }

    // ---- decoder ----
    for (int t = 0; t < 25; t++) {
        layer<160>(tid, lane, wm, wn, smem_base, sH, sB, sC0, sBias + 2 * NG,
                   g_S + OFF_D0, g_S + OFF_D1, 0, sc, ph);
        layer<256>(tid, lane, wm, wn, smem_base, sH, sB, sC1, sBias + 3 * NG,
                   g_S + OFF_D1, (t < 24) ? g_S + OFF_D0 : nullptr, 160, sc, ph);
        __syncthreads();   // h1 complete before projection

        // projection: pred = h1 @ outW^T + outb   (16 warps x 4 rows)
#pragma unroll
        for (int r4 = 0; r4 < 4; r4++) {
            int mloc = warp * 4 + r4;
            float a0 = 0.0f, a1 = 0.0f;
#pragma unroll
            for (int j = 0; j < 4; j++) {
                int k = lane + 32 * j;
                float hv = __half2float(sH[mloc * LDA + 160 + k]);
                a0 += hv * sOW[k];
                a1 += hv * sOW[128 + k];
            }
#pragma unroll
            for (int off = 16; off > 0; off >>= 1) {
                a0 += __shfl_down_sync(0xffffffffu, a0, off);
                a1 += __shfl_down_sync(0xffffffffu, a1, off);
            }
            if (lane == 0) {
                a0 += sOB[0];
                a1 += sOB[1];
                long m = m0 + mloc;
                dout[m * 50 + t * 2 + 0] = a0;
                dout[m * 50 + t * 2 + 1] = a1;
                sH[mloc * LDA + 128] = __float2half(a0);
                sH[mloc * LDA + 129] = __float2half(a1);
            }
        }
    }

    __syncthreads();
    if (tid == 0) {
        mbar_inval(smem_base + SMO_MB);
        mbar_inval(smem_base + SMO_MB + 8);
    }
}

// ---------------- host ----------------
extern "C" void kernel_launch(void* const* d_in, const int* in_sizes, int n_in,
                              void* d_out, int out_size)
{
    const float* target = (const float*)d_in[0];
    const float* eWih0 = (const float*)d_in[4];
    const float* eWhh0 = (const float*)d_in[5];
    const float* ebih0 = (const float*)d_in[6];
    const float* ebhh0 = (const float*)d_in[7];
    const float* eWih1 = (const float*)d_in[8];
    const float* eWhh1 = (const float*)d_in[9];
    const float* ebih1 = (const float*)d_in[10];
    const float* ebhh1 = (const float*)d_in[11];
    const float* dWih0 = (const float*)d_in[12];
    const float* dWhh0 = (const float*)d_in[13];
    const float* dbih0 = (const float*)d_in[14];
    const float* dbhh0 = (const float*)d_in[15];
    const float* dWih1 = (const float*)d_in[16];
    const float* dWhh1 = (const float*)d_in[17];
    const float* dbih1 = (const float*)d_in[18];
    const float* dbhh1 = (const float*)d_in[19];
    const float* outW  = (const float*)d_in[20];
    const float* outb  = (const float*)d_in[21];
    float* out = (float*)d_out;

    cudaFuncSetAttribute(lstm_fused, cudaFuncAttributeMaxDynamicSharedMemorySize, SMEM_TOTAL);

    build_weights<<<26, NT>>>(eWih0, eWhh0, ebih0, ebhh0,
                              eWih1, eWhh1, ebih1, ebhh1,
                              dWih0, dWhh0, dbih0, dbhh0,
                              dWih1, dWhh1, dbih1, dbhh1);

    lstm_fused<<<BATCH / MT, NT, SMEM_TOTAL>>>(target, outW, outb, out);
}

// round 8
// speedup vs baseline: 3.9967x; 1.0104x over previous
#include <cuda_runtime.h>
#include <cuda_fp16.h>
#include <cstdint>

#define BATCH 65536
#define NG 512
#define MT 64
#define LDA 296          // sH leading dim (halves): conflict-free LDSM
#define LDC 130          // c leading dim (floats): conflict-free epilogue
#define NT 512           // 16 warps
#define SLABH 16384      // halves per packed slab (512 rows x 32 K-cols, SW64-swizzled)
#define SLABB 32768      // bytes per slab
#define TOTAL_SLABS 585  // 45 step-pairs x 13 slabs

// ---- packed swizzled weight slabs in gmem: [E0:5][E1:8][D0:5][D1:8] ----
__device__ __align__(16) __half g_S[26 * SLABH];
__device__ float g_bias[4 * NG];

// ---- smem map (bytes) ----
#define SMO_H    0          // 64 x 296 fp16 (37888)
#define SMO_B    37888      // 3 x 32768 slab buffers (98304)
#define SMO_C0   136192     // 64 x 130 fp32 (33280)
#define SMO_C1   169472     // 64 x 130 fp32 (33280)
#define SMO_BIAS 202752     // 4 x 512 fp32 (8192)
#define SMO_OW   210944     // 256 fp32 (1024)
#define SMO_OB   211968     // 2 fp32
#define SMO_MBF  211984     // 3 full mbarriers
#define SMO_MBE  212008     // 3 empty mbarriers
#define SMEM_TOTAL 212032

// ---------------- helpers ----------------
__device__ __forceinline__ float tanha(float x) {
    float y; asm("tanh.approx.f32 %0, %1;" : "=f"(y) : "f"(x)); return y;
}
__device__ __forceinline__ float sigf(float x) {
    return fmaf(0.5f, tanha(0.5f * x), 0.5f);
}
__device__ __forceinline__ unsigned smem_u32(const void* p) {
    return (unsigned)__cvta_generic_to_shared(p);
}
__device__ __forceinline__ void mbar_init(uint32_t a, uint32_t c) {
    asm volatile("mbarrier.init.shared.b64 [%0], %1;" :: "r"(a), "r"(c) : "memory");
}
__device__ __forceinline__ void mbar_inval(uint32_t a) {
    asm volatile("mbarrier.inval.shared.b64 [%0];" :: "r"(a) : "memory");
}
__device__ __forceinline__ void mbar_expect_tx(uint32_t a, uint32_t bytes) {
    asm volatile("mbarrier.arrive.expect_tx.shared.b64 _, [%0], %1;"
                 :: "r"(a), "r"(bytes) : "memory");
}
__device__ __forceinline__ void mbar_arrive(uint32_t a) {
    asm volatile("mbarrier.arrive.shared.b64 _, [%0];" :: "r"(a) : "memory");
}
__device__ __forceinline__ void mbar_wait(uint32_t mbar, int parity) {
    uint32_t done;
    asm volatile(
        "{\n\t.reg .pred p;\n\t"
        "mbarrier.try_wait.parity.acquire.cta.shared::cta.b64 p, [%1], %2;\n\t"
        "selp.b32 %0, 1, 0, p;\n\t}"
        : "=r"(done) : "r"(mbar), "r"((uint32_t)parity) : "memory");
    if (!done) {
        asm volatile(
            "{\n\t.reg .pred P1;\n\t"
            "WAIT_LOOP_%=:\n\t"
            "mbarrier.try_wait.parity.acquire.cta.shared::cta.b64 P1, [%0], %1, 0x989680;\n\t"
            "@P1 bra.uni WAIT_DONE_%=;\n\t"
            "bra.uni WAIT_LOOP_%=;\n\t"
            "WAIT_DONE_%=:\n\t}"
            :: "r"(mbar), "r"((uint32_t)parity) : "memory");
    }
}
__device__ __forceinline__ void bulk_g2s(uint32_t dst, const void* src,
                                         uint32_t bytes, uint32_t mbar) {
    asm volatile(
        "cp.async.bulk.shared::cta.global.mbarrier::complete_tx::bytes [%0], [%1], %2, [%3];"
        :: "r"(dst), "l"(src), "r"(bytes), "r"(mbar) : "memory");
}
__device__ __forceinline__ void ldsm4(unsigned addr, unsigned& r0, unsigned& r1,
                                      unsigned& r2, unsigned& r3) {
    asm volatile("ldmatrix.sync.aligned.m8n8.x4.shared.b16 {%0,%1,%2,%3}, [%4];"
                 : "=r"(r0), "=r"(r1), "=r"(r2), "=r"(r3) : "r"(addr));
}
__device__ __forceinline__ void mma16816(float* d, const unsigned* a, unsigned b0, unsigned b1) {
    asm volatile(
        "mma.sync.aligned.m16n8k16.row.col.f32.f16.f16.f32 "
        "{%0,%1,%2,%3},{%4,%5,%6,%7},{%8,%9},{%0,%1,%2,%3};"
        : "+f"(d[0]), "+f"(d[1]), "+f"(d[2]), "+f"(d[3])
        : "r"(a[0]), "r"(a[1]), "r"(a[2]), "r"(a[3]), "r"(b0), "r"(b1));
}
// global slab index -> gmem source
__device__ __forceinline__ const __half* slab_src(int gg) {
    int sp = gg / 13;
    int w  = gg - sp * 13;
    return g_S + (size_t)(((sp < 20) ? 0 : 13) + w) * SLABH;
}

// ---------------- prep: gate-interleave + K-fold + SW64 swizzle ----------------
// n' = h*4 + gate (order i,f,g,o); row n' = row gate*128+h of original.
__global__ void build_weights(
    const float* __restrict__ eWih0, const float* __restrict__ eWhh0,
    const float* __restrict__ ebih0, const float* __restrict__ ebhh0,
    const float* __restrict__ eWih1, const float* __restrict__ eWhh1,
    const float* __restrict__ ebih1, const float* __restrict__ ebhh1,
    const float* __restrict__ dWih0, const float* __restrict__ dWhh0,
    const float* __restrict__ dbih0, const float* __restrict__ dbhh0,
    const float* __restrict__ dWih1, const float* __restrict__ dWhh1,
    const float* __restrict__ dbih1, const float* __restrict__ dbhh1)
{
    int sb = blockIdx.x;        // 0..25
    int phase, ks;
    if (sb < 5)       { phase = 0; ks = sb; }
    else if (sb < 13) { phase = 1; ks = sb - 5; }
    else if (sb < 18) { phase = 2; ks = sb - 13; }
    else              { phase = 3; ks = sb - 18; }
    char* dst = (char*)(g_S + (size_t)sb * SLABH);

    int np = threadIdx.x;       // 0..511
    int gate = np & 3, h = np >> 2;
    int src = gate * 128 + h;

    for (int c = 0; c < 32; c++) {
        int kglob = ks * 32 + c;
        float v = 0.0f;
        if (phase == 0) {
            if (kglob < 128) v = eWhh0[src * 128 + kglob];
            else if (kglob < 135) v = eWih0[src * 7 + (kglob - 128)];
        } else if (phase == 1) {
            v = (kglob < 128) ? eWih1[src * 128 + kglob] : eWhh1[src * 128 + kglob - 128];
        } else if (phase == 2) {
            if (kglob < 128) v = dWhh0[src * 128 + kglob];
            else if (kglob < 130) v = dWih0[src * 2 + (kglob - 128)];
        } else {
            v = (kglob < 128) ? dWih1[src * 128 + kglob] : dWhh1[src * 128 + kglob - 128];
        }
        int off = np * 64 + c * 2;
        off ^= (off >> 3) & 0x30;     // SW64 swizzle
        *(__half*)(dst + off) = __float2half(v);
    }
    if (ks == 0) {
        const float* bi = (phase == 0) ? ebih0 : (phase == 1) ? ebih1 : (phase == 2) ? dbih0 : dbih1;
        const float* bh = (phase == 0) ? ebhh0 : (phase == 1) ? ebhh1 : (phase == 2) ? dbhh0 : dbhh1;
        g_bias[phase * NG + np] = bi[src] + bh[src];
    }
}

// ---------------- one LSTM layer step (pipelined slabs, no per-slab syncthreads) ----------------
// A = sH; layer0 (KG=160): cols 0..159; layer1 (KG=256): h0 cols 0..127, h1 cols 160..287.
// Ends with __syncthreads + epilogue (no trailing sync; caller inserts).
template <int KG>
__device__ __forceinline__ void layer(
    int tid, int lane, int wm, int wn, uint32_t smem_base,
    __half* sH, float* sC, const float* bias, int hOff,
    int& g, int& b, int& pf, int& pe)
{
    constexpr int NS = KG / 32;
    const uint32_t mbF = smem_base + SMO_MBF;
    const uint32_t mbE = smem_base + SMO_MBE;

    float acc[2][8][4];
#pragma unroll
    for (int ni = 0; ni < 8; ni++) {
        int c0 = wn * 64 + ni * 8 + 2 * (lane & 3);
        float b0 = bias[c0], b1 = bias[c0 + 1];
#pragma unroll
        for (int mi = 0; mi < 2; mi++) {
            acc[mi][ni][0] = b0; acc[mi][ni][1] = b1;
            acc[mi][ni][2] = b0; acc[mi][ni][3] = b1;
        }
    }

#pragma unroll
    for (int ks = 0; ks < NS; ks++) {
        // consume slab g from buffer b
        mbar_wait(mbF + b * 8, (pf >> b) & 1);
        pf ^= (1 << b);

        int acol = ks * 32;
        if (KG == 256 && ks >= 4) acol += 32;   // h1 at cols 160..287
        const uint32_t bbase = smem_base + SMO_B + b * SLABB;

#pragma unroll
        for (int kf = 0; kf < 2; kf++) {
            unsigned a[2][4];
#pragma unroll
            for (int mi = 0; mi < 2; mi++) {
                unsigned addr = smem_u32(sH + (wm * 32 + mi * 16 + (lane & 15)) * LDA
                                            + acol + kf * 16 + (lane >> 4) * 8);
                ldsm4(addr, a[mi][0], a[mi][1], a[mi][2], a[mi][3]);
            }
#pragma unroll
            for (int nq = 0; nq < 4; nq++) {
                int nrow = wn * 64 + nq * 16 + (lane & 15);
                int off = nrow * 64 + (kf * 2 + (lane >> 4)) * 16;
                off ^= (off >> 3) & 0x30;                 // SW64 swizzle
                unsigned b0, b1, b2, b3;
                ldsm4(bbase + off, b0, b1, b2, b3);
#pragma unroll
                for (int mi = 0; mi < 2; mi++) {
                    mma16816(acc[mi][2 * nq],     a[mi], b0, b2);
                    mma16816(acc[mi][2 * nq + 1], a[mi], b1, b3);
                }
            }
        }
        if (lane == 0) mbar_arrive(mbE + b * 8);   // this warp done reading buffer b

        // producer: refill buffer b with slab g+3 once all 16 warps arrived
        bool more = (g + 3 < TOTAL_SLABS);
        if (tid == 0 && more) {
            mbar_wait(mbE + b * 8, (pe >> b) & 1);
            mbar_expect_tx(mbF + b * 8, SLABB);
            bulk_g2s(smem_base + SMO_B + b * SLABB, slab_src(g + 3), SLABB, mbF + b * 8);
        }
        if (more) pe ^= (1 << b);

        b = (b == 2) ? 0 : b + 1;
        g++;
    }
    __syncthreads();   // all warps' A-reads done before epilogue rewrites h

    // register epilogue: lane-pair exchange gathers all 4 gates per (row, hidden)
    int odd = lane & 1;
#pragma unroll
    for (int mi = 0; mi < 2; mi++) {
#pragma unroll
        for (int ni = 0; ni < 8; ni++) {
            float* d = acc[mi][ni];
            float e1 = __shfl_xor_sync(0xffffffffu, odd ? d[0] : d[2], 1);
            float e2 = __shfl_xor_sync(0xffffffffu, odd ? d[1] : d[3], 1);
            float pi = odd ? e1 : d[0];
            float pf2 = odd ? e2 : d[1];
            float pg = odd ? d[2] : e1;
            float po = odd ? d[3] : e2;
            int mloc = wm * 32 + mi * 16 + (lane >> 2) + 8 * odd;
            int hidx = wn * 16 + ni * 2 + ((lane >> 1) & 1);
            float cc = sigf(pf2) * sC[mloc * LDC + hidx] + sigf(pi) * tanha(pg);
            sC[mloc * LDC + hidx] = cc;
            sH[mloc * LDA + hOff + hidx] = __float2half(sigf(po) * tanha(cc));
        }
    }
}

// ---------------- the fused full-network kernel ----------------
__global__ __launch_bounds__(NT, 1)
void lstm_fused(const float* __restrict__ target,
                const float* __restrict__ outW, const float* __restrict__ outb,
                float* __restrict__ dout)
{
    extern __shared__ char smem[];
    uint32_t smem_base = smem_u32(smem);
    __half* sH    = (__half*)(smem + SMO_H);
    float*  sC0   = (float*)(smem + SMO_C0);
    float*  sC1   = (float*)(smem + SMO_C1);
    float*  sBias = (float*)(smem + SMO_BIAS);
    float*  sOW   = (float*)(smem + SMO_OW);
    float*  sOB   = (float*)(smem + SMO_OB);

    int tid  = threadIdx.x;
    int warp = tid >> 5, lane = tid & 31;
    int wm = warp >> 3, wn = warp & 7;
    long m0 = (long)blockIdx.x * MT;

    // ---- init ----
    if (tid == 0) {
#pragma unroll
        for (int i = 0; i < 3; i++) {
            mbar_init(smem_base + SMO_MBF + i * 8, 1);    // tx-based full
            mbar_init(smem_base + SMO_MBE + i * 8, 16);   // 16 warp arrivals
        }
    }
    for (int i = tid; i < MT * LDA; i += NT) sH[i] = __float2half(0.0f);
    for (int i = tid; i < MT * LDC; i += NT) { sC0[i] = 0.0f; sC1[i] = 0.0f; }
    for (int i = tid; i < 4 * NG; i += NT) sBias[i] = g_bias[i];
    if (tid < 256) sOW[tid] = outW[tid];
    if (tid < 2) sOB[tid] = outb[tid];
    __syncthreads();

    // prologue: fill all 3 buffers with slabs 0,1,2
    if (tid == 0) {
#pragma unroll
        for (int i = 0; i < 3; i++) {
            mbar_expect_tx(smem_base + SMO_MBF + i * 8, SLABB);
            bulk_g2s(smem_base + SMO_B + i * SLABB, slab_src(i), SLABB,
                     smem_base + SMO_MBF + i * 8);
        }
    }

    int g = 0, b = 0, pf = 0, pe = 0;

    // ---- encoder: 20 steps ----
    for (int t = 0; t < 20; t++) {
        for (int i = tid; i < MT * 7; i += NT) {    // stage x -> sH cols 128..134
            int m = i / 7, k = i - m * 7;
            sH[m * LDA + 128 + k] = __float2half(target[(m0 + m) * 140 + t * 7 + k]);
        }
        __syncthreads();                            // x visible to all A-loads
        layer<160>(tid, lane, wm, wn, smem_base, sH, sC0, sBias, 0, g, b, pf, pe);
        __syncthreads();                            // h0 (epi0) visible to layer1
        layer<256>(tid, lane, wm, wn, smem_base, sH, sC1, sBias + NG, 160, g, b, pf, pe);
        // no sync needed: epi1 writes cols 160+, next x-stage writes 128..134 (disjoint)
    }

    // zero pred zone for first decoder step (stale x cols 130..134 hit zero weights)
    for (int i = tid; i < MT * 2; i += NT) {
        int m = i >> 1, k = i & 1;
        sH[m * LDA + 128 + k] = __float2half(0.0f);
    }
    __syncthreads();

    // ---- decoder: 25 steps ----
    for (int t = 0; t < 25; t++) {
        layer<160>(tid, lane, wm, wn, smem_base, sH, sC0, sBias + 2 * NG, 0, g, b, pf, pe);
        __syncthreads();                            // h0 visible to layer1
        layer<256>(tid, lane, wm, wn, smem_base, sH, sC1, sBias + 3 * NG, 160, g, b, pf, pe);
        __syncthreads();                            // h1 (epi1) visible to projection

        // projection: pred = h1 @ outW^T + outb   (16 warps x 4 rows)
#pragma unroll
        for (int r4 = 0; r4 < 4; r4++) {
            int mloc = warp * 4 + r4;
            float a0 = 0.0f, a1 = 0.0f;
#pragma unroll
            for (int j = 0; j < 4; j++) {
                int k = lane + 32 * j;
                float hv = __half2float(sH[mloc * LDA + 160 + k]);
                a0 += hv * sOW[k];
                a1 += hv * sOW[128 + k];
            }
#pragma unroll
            for (int off = 16; off > 0; off >>= 1) {
                a0 += __shfl_down_sync(0xffffffffu, a0, off);
                a1 += __shfl_down_sync(0xffffffffu, a1, off);
            }
            if (lane == 0) {
                a0 += sOB[0];
                a1 += sOB[1];
                long m = m0 + mloc;
                dout[m * 50 + t * 2 + 0] = a0;
                dout[m * 50 + t * 2 + 1] = a1;
                sH[mloc * LDA + 128] = __float2half(a0);
                sH[mloc * LDA + 129] = __float2half(a1);
            }
        }
        __syncthreads();                            // pred visible to next layer0
    }

    if (tid == 0) {
#pragma unroll
        for (int i = 0; i < 3; i++) {
            mbar_inval(smem_base + SMO_MBF + i * 8);
            mbar_inval(smem_base + SMO_MBE + i * 8);
        }
    }
}

// ---------------- host ----------------
extern "C" void kernel_launch(void* const* d_in, const int* in_sizes, int n_in,
                              void* d_out, int out_size)
{
    const float* target = (const float*)d_in[0];
    const float* eWih0 = (const float*)d_in[4];
    const float* eWhh0 = (const float*)d_in[5];
    const float* ebih0 = (const float*)d_in[6];
    const float* ebhh0 = (const float*)d_in[7];
    const float* eWih1 = (const float*)d_in[8];
    const float* eWhh1 = (const float*)d_in[9];
    const float* ebih1 = (const float*)d_in[10];
    const float* ebhh1 = (const float*)d_in[11];
    const float* dWih0 = (const float*)d_in[12];
    const float* dWhh0 = (const float*)d_in[13];
    const float* dbih0 = (const float*)d_in[14];
    const float* dbhh0 = (const float*)d_in[15];
    const float* dWih1 = (const float*)d_in[16];
    const float* dWhh1 = (const float*)d_in[17];
    const float* dbih1 = (const float*)d_in[18];
    const float* dbhh1 = (const float*)d_in[19];
    const float* outW  = (const float*)d_in[20];
    const float* outb  = (const float*)d_in[21];
    float* out = (float*)d_out;

    cudaFuncSetAttribute(lstm_fused, cudaFuncAttributeMaxDynamicSharedMemorySize, SMEM_TOTAL);

    build_weights<<<26, NT>>>(eWih0, eWhh0, ebih0, ebhh0,
                              eWih1, eWhh1, ebih1, ebhh1,
                              dWih0, dWhh0, dbih0, dbhh0,
                              dWih1, dWhh1, dbih1, dbhh1);

    lstm_fused<<<BATCH / MT, NT, SMEM_TOTAL>>>(target, outW, outb, out);
}

// round 9
// speedup vs baseline: 4.0498x; 1.0133x over previous
#include <cuda_runtime.h>
#include <cuda_fp16.h>
#include <cstdint>

#define BATCH 65536
#define NG 512
#define MT 64
#define LDA 296          // sH leading dim (halves): conflict-free LDSM
#define LDC 130          // c leading dim (floats)
#define NT 512           // 16 warps
#define SLABH 16384      // halves per packed slab (512 x 32, SW64-swizzled)
#define SLABB 32768
#define TOTAL_SLABS 585  // 45 step-pairs x 13 slabs

// ---- packed swizzled weight slabs in gmem, in CONSUMPTION order ----
// per pair: [L0 ks0..4][L1 ks4..7][L1 ks0..3];  E-block pos 0..12, D-block pos 13..25
__device__ __align__(16) __half g_S[26 * SLABH];
__device__ float g_bias[4 * NG];

// ---- smem map (bytes) ----
#define SMO_H    0          // 64 x 296 fp16
#define SMO_B    37888      // 3 x 32768 slab buffers
#define SMO_C0   136192     // 64 x 130 fp32
#define SMO_C1   169472     // 64 x 130 fp32
#define SMO_BIAS 202752     // 4 x 512 fp32
#define SMO_OW   210944     // 256 fp32
#define SMO_OB   211968     // 2 fp32
#define SMO_MBF  211984     // 3 full mbarriers
#define SMO_MBE  212008     // 3 empty mbarriers
#define SMEM_TOTAL 212032

// ---------------- helpers ----------------
__device__ __forceinline__ unsigned smem_u32(const void* p) {
    return (unsigned)__cvta_generic_to_shared(p);
}
__device__ __forceinline__ unsigned tanh2u(unsigned x) {
    unsigned y; asm("tanh.approx.f16x2 %0, %1;" : "=r"(y) : "r"(x)); return y;
}
__device__ __forceinline__ unsigned pack2(float a, float b) {
    __half2 h = __floats2half2_rn(a, b);
    return *reinterpret_cast<unsigned*>(&h);
}
__device__ __forceinline__ __half2 u2h(unsigned u) {
    return *reinterpret_cast<__half2*>(&u);
}
__device__ __forceinline__ void mbar_init(uint32_t a, uint32_t c) {
    asm volatile("mbarrier.init.shared.b64 [%0], %1;" :: "r"(a), "r"(c) : "memory");
}
__device__ __forceinline__ void mbar_inval(uint32_t a) {
    asm volatile("mbarrier.inval.shared.b64 [%0];" :: "r"(a) : "memory");
}
__device__ __forceinline__ void mbar_expect_tx(uint32_t a, uint32_t bytes) {
    asm volatile("mbarrier.arrive.expect_tx.shared.b64 _, [%0], %1;"
                 :: "r"(a), "r"(bytes) : "memory");
}
__device__ __forceinline__ void mbar_arrive(uint32_t a) {
    asm volatile("mbarrier.arrive.shared.b64 _, [%0];" :: "r"(a) : "memory");
}
__device__ __forceinline__ void mbar_wait(uint32_t mbar, int parity) {
    uint32_t done;
    asm volatile(
        "{\n\t.reg .pred p;\n\t"
        "mbarrier.try_wait.parity.acquire.cta.shared::cta.b64 p, [%1], %2;\n\t"
        "selp.b32 %0, 1, 0, p;\n\t}"
        : "=r"(done) : "r"(mbar), "r"((uint32_t)parity) : "memory");
    if (!done) {
        asm volatile(
            "{\n\t.reg .pred P1;\n\t"
            "WAIT_LOOP_%=:\n\t"
            "mbarrier.try_wait.parity.acquire.cta.shared::cta.b64 P1, [%0], %1, 0x989680;\n\t"
            "@P1 bra.uni WAIT_DONE_%=;\n\t"
            "bra.uni WAIT_LOOP_%=;\n\t"
            "WAIT_DONE_%=:\n\t}"
            :: "r"(mbar), "r"((uint32_t)parity) : "memory");
    }
}
__device__ __forceinline__ void bulk_g2s(uint32_t dst, const void* src,
                                         uint32_t bytes, uint32_t mbar) {
    asm volatile(
        "cp.async.bulk.shared::cta.global.mbarrier::complete_tx::bytes [%0], [%1], %2, [%3];"
        :: "r"(dst), "l"(src), "r"(bytes), "r"(mbar) : "memory");
}
__device__ __forceinline__ void ldsm4(unsigned addr, unsigned& r0, unsigned& r1,
                                      unsigned& r2, unsigned& r3) {
    asm volatile("ldmatrix.sync.aligned.m8n8.x4.shared.b16 {%0,%1,%2,%3}, [%4];"
                 : "=r"(r0), "=r"(r1), "=r"(r2), "=r"(r3) : "r"(addr));
}
__device__ __forceinline__ void mma16816(float* d, const unsigned* a, unsigned b0, unsigned b1) {
    asm volatile(
        "mma.sync.aligned.m16n8k16.row.col.f32.f16.f16.f32 "
        "{%0,%1,%2,%3},{%4,%5,%6,%7},{%8,%9},{%0,%1,%2,%3};"
        : "+f"(d[0]), "+f"(d[1]), "+f"(d[2]), "+f"(d[3])
        : "r"(a[0]), "r"(a[1]), "r"(a[2]), "r"(a[3]), "r"(b0), "r"(b1));
}
__device__ __forceinline__ const __half* slab_src(int gg) {
    int sp = gg / 13;
    int w  = gg - sp * 13;
    return g_S + (size_t)(((sp < 20) ? 0 : 13) + w) * SLABH;
}

// ---------------- prep: gate-interleave + K-fold + SW64 swizzle + sig-prescale ----------------
// n' = h*4 + gate (i,f,g,o). Gates i,f,o (and their biases) pre-scaled by 0.5 so
// sigmoid(x) = 0.5 + 0.5*tanh(acc) directly. Storage position = consumption order.
__global__ void build_weights(
    const float* __restrict__ eWih0, const float* __restrict__ eWhh0,
    const float* __restrict__ ebih0, const float* __restrict__ ebhh0,
    const float* __restrict__ eWih1, const float* __restrict__ eWhh1,
    const float* __restrict__ ebih1, const float* __restrict__ ebhh1,
    const float* __restrict__ dWih0, const float* __restrict__ dWhh0,
    const float* __restrict__ dbih0, const float* __restrict__ dbhh0,
    const float* __restrict__ dWih1, const float* __restrict__ dWhh1,
    const float* __restrict__ dbih1, const float* __restrict__ dbhh1)
{
    int sb = blockIdx.x;        // 0..25
    int phase, ks;
    if (sb < 5)       { phase = 0; ks = sb; }
    else if (sb < 13) { phase = 1; ks = sb - 5; }
    else if (sb < 18) { phase = 2; ks = sb - 13; }
    else              { phase = 3; ks = sb - 18; }

    // storage position (consumption order)
    int pos;
    if (phase == 0)      pos = ks;
    else if (phase == 1) pos = (ks >= 4) ? 5 + (ks - 4) : 9 + ks;
    else if (phase == 2) pos = 13 + ks;
    else                 pos = (ks >= 4) ? 18 + (ks - 4) : 22 + ks;
    char* dst = (char*)(g_S + (size_t)pos * SLABH);

    int np = threadIdx.x;       // 0..511
    int gate = np & 3, h = np >> 2;
    int src = gate * 128 + h;
    float scale = (gate == 2) ? 1.0f : 0.5f;   // sigmoid pre-scale for i,f,o

    for (int c = 0; c < 32; c++) {
        int kglob = ks * 32 + c;
        float v = 0.0f;
        if (phase == 0) {
            if (kglob < 128) v = eWhh0[src * 128 + kglob];
            else if (kglob < 135) v = eWih0[src * 7 + (kglob - 128)];
        } else if (phase == 1) {
            v = (kglob < 128) ? eWih1[src * 128 + kglob] : eWhh1[src * 128 + kglob - 128];
        } else if (phase == 2) {
            if (kglob < 128) v = dWhh0[src * 128 + kglob];
            else if (kglob < 130) v = dWih0[src * 2 + (kglob - 128)];
        } else {
            v = (kglob < 128) ? dWih1[src * 128 + kglob] : dWhh1[src * 128 + kglob - 128];
        }
        int off = np * 64 + c * 2;
        off ^= (off >> 3) & 0x30;     // SW64 swizzle
        *(__half*)(dst + off) = __float2half(v * scale);
    }
    if (ks == 0) {
        const float* bi = (phase == 0) ? ebih0 : (phase == 1) ? ebih1 : (phase == 2) ? dbih0 : dbih1;
        const float* bh = (phase == 0) ? ebhh0 : (phase == 1) ? ebhh1 : (phase == 2) ? dbhh0 : dbhh1;
        g_bias[phase * NG + np] = (bi[src] + bh[src]) * scale;
    }
}

// ---------------- acc init with bias ----------------
__device__ __forceinline__ void init_acc(float (&acc)[2][8][4], const float* bias,
                                         int lane, int wn)
{
#pragma unroll
    for (int ni = 0; ni < 8; ni++) {
        int c0 = wn * 64 + ni * 8 + 2 * (lane & 3);
        float b0 = bias[c0], b1 = bias[c0 + 1];
#pragma unroll
        for (int mi = 0; mi < 2; mi++) {
            acc[mi][ni][0] = b0; acc[mi][ni][1] = b1;
            acc[mi][ni][2] = b0; acc[mi][ni][3] = b1;
        }
    }
}

// ---------------- NSL slabs of MMA; A cols = ACOL0 + j*32 ----------------
template <int NSL, int ACOL0>
__device__ __forceinline__ void mma_slabs(
    float (&acc)[2][8][4], int tid, int lane, int wm, int wn, uint32_t smem_base,
    __half* sH, int& g, int& b, int& pfull, int& pempt)
{
    const uint32_t mbF = smem_base + SMO_MBF;
    const uint32_t mbE = smem_base + SMO_MBE;
#pragma unroll
    for (int j = 0; j < NSL; j++) {
        mbar_wait(mbF + b * 8, (pfull >> b) & 1);
        pfull ^= (1 << b);

        const int acol = ACOL0 + j * 32;
        const uint32_t bbase = smem_base + SMO_B + b * SLABB;

#pragma unroll
        for (int kf = 0; kf < 2; kf++) {
            unsigned a[2][4];
#pragma unroll
            for (int mi = 0; mi < 2; mi++) {
                unsigned addr = smem_u32(sH + (wm * 32 + mi * 16 + (lane & 15)) * LDA
                                            + acol + kf * 16 + (lane >> 4) * 8);
                ldsm4(addr, a[mi][0], a[mi][1], a[mi][2], a[mi][3]);
            }
#pragma unroll
            for (int nq = 0; nq < 4; nq++) {
                int nrow = wn * 64 + nq * 16 + (lane & 15);
                int off = nrow * 64 + (kf * 2 + (lane >> 4)) * 16;
                off ^= (off >> 3) & 0x30;
                unsigned b0, b1, b2, b3;
                ldsm4(bbase + off, b0, b1, b2, b3);
#pragma unroll
                for (int mi = 0; mi < 2; mi++) {
                    mma16816(acc[mi][2 * nq],     a[mi], b0, b2);
                    mma16816(acc[mi][2 * nq + 1], a[mi], b1, b3);
                }
            }
        }
        if (lane == 0) mbar_arrive(mbE + b * 8);

        bool more = (g + 3 < TOTAL_SLABS);
        if (tid == 0 && more) {
            mbar_wait(mbE + b * 8, (pempt >> b) & 1);
            mbar_expect_tx(mbF + b * 8, SLABB);
            bulk_g2s(smem_base + SMO_B + b * SLABB, slab_src(g + 3), SLABB, mbF + b * 8);
        }
        if (more) pempt ^= (1 << b);

        b = (b == 2) ? 0 : b + 1;
        g++;
    }
}

// ---------------- f16x2 epilogue: 2.5 MUFU per unit ----------------
__device__ __forceinline__ void epilogue(
    float (&acc)[2][8][4], int lane, int wm, int wn,
    __half* sH, float* sC, int hOff)
{
    const int odd = lane & 1;
    const __half2 h05 = __floats2half2_rn(0.5f, 0.5f);
#pragma unroll
    for (int mi = 0; mi < 2; mi++) {
        int mloc = wm * 32 + mi * 16 + (lane >> 2) + 8 * odd;
#pragma unroll
        for (int p2 = 0; p2 < 4; p2++) {
            float pi0, pi1, pf0, pf1, pg0, pg1, po0, po1;
#pragma unroll
            for (int u = 0; u < 2; u++) {
                float* d = acc[mi][p2 * 2 + u];
                float e1 = __shfl_xor_sync(0xffffffffu, odd ? d[0] : d[2], 1);
                float e2 = __shfl_xor_sync(0xffffffffu, odd ? d[1] : d[3], 1);
                float vi = odd ? e1 : d[0];
                float vf = odd ? e2 : d[1];
                float vg = odd ? d[2] : e1;
                float vo = odd ? d[3] : e2;
                if (u == 0) { pi0 = vi; pf0 = vf; pg0 = vg; po0 = vo; }
                else        { pi1 = vi; pf1 = vf; pg1 = vg; po1 = vo; }
            }
            // weights for i,f,o pre-scaled by 0.5 => sig = 0.5 + 0.5*tanh(acc)
            __half2 si = __hfma2(u2h(tanh2u(pack2(pi0, pi1))), h05, h05);
            __half2 sf = __hfma2(u2h(tanh2u(pack2(pf0, pf1))), h05, h05);
            __half2 tg = u2h(tanh2u(pack2(pg0, pg1)));
            __half2 so = __hfma2(u2h(tanh2u(pack2(po0, po1))), h05, h05);
            float2 fsi = __half22float2(si);
            float2 fsf = __half22float2(sf);
            float2 ftg = __half22float2(tg);
            int hx0 = wn * 16 + (p2 * 2) * 2 + ((lane >> 1) & 1);
            int hx1 = hx0 + 2;
            float cc0 = fsf.x * sC[mloc * LDC + hx0] + fsi.x * ftg.x;
            float cc1 = fsf.y * sC[mloc * LDC + hx1] + fsi.y * ftg.y;
            sC[mloc * LDC + hx0] = cc0;
            sC[mloc * LDC + hx1] = cc1;
            __half2 hh = __hmul2(u2h(tanh2u(pack2(cc0, cc1))), so);
            sH[mloc * LDA + hOff + hx0] = __low2half(hh);
            sH[mloc * LDA + hOff + hx1] = __high2half(hh);
        }
    }
}

// ---------------- the fused full-network kernel ----------------
__global__ __launch_bounds__(NT, 1)
void lstm_fused(const float* __restrict__ target,
                const float* __restrict__ outW, const float* __restrict__ outb,
                float* __restrict__ dout)
{
    extern __shared__ char smem[];
    uint32_t smem_base = smem_u32(smem);
    __half* sH    = (__half*)(smem + SMO_H);
    float*  sC0   = (float*)(smem + SMO_C0);
    float*  sC1   = (float*)(smem + SMO_C1);
    float*  sBias = (float*)(smem + SMO_BIAS);
    float*  sOW   = (float*)(smem + SMO_OW);
    float*  sOB   = (float*)(smem + SMO_OB);

    int tid  = threadIdx.x;
    int warp = tid >> 5, lane = tid & 31;
    int wm = warp >> 3, wn = warp & 7;
    long m0 = (long)blockIdx.x * MT;

    // ---- init ----
    if (tid == 0) {
#pragma unroll
        for (int i = 0; i < 3; i++) {
            mbar_init(smem_base + SMO_MBF + i * 8, 1);
            mbar_init(smem_base + SMO_MBE + i * 8, 16);
        }
    }
    for (int i = tid; i < MT * LDA; i += NT) sH[i] = __float2half(0.0f);
    for (int i = tid; i < MT * LDC; i += NT) { sC0[i] = 0.0f; sC1[i] = 0.0f; }
    for (int i = tid; i < 4 * NG; i += NT) sBias[i] = g_bias[i];
    if (tid < 256) sOW[tid] = outW[tid];
    if (tid < 2) sOB[tid] = outb[tid];
    // stage x(0)
    for (int i = tid; i < MT * 7; i += NT) {
        int m = i / 7, k = i - m * 7;
        sH[m * LDA + 128 + k] = __float2half(target[(m0 + m) * 140 + k]);
    }
    __syncthreads();

    if (tid == 0) {
#pragma unroll
        for (int i = 0; i < 3; i++) {
            mbar_expect_tx(smem_base + SMO_MBF + i * 8, SLABB);
            bulk_g2s(smem_base + SMO_B + i * SLABB, slab_src(i), SLABB,
                     smem_base + SMO_MBF + i * 8);
        }
    }

    int g = 0, b = 0, pfull = 0, pempt = 0;
    float acc[2][8][4];

    // ---- encoder: 20 steps ----
    for (int t = 0; t < 20; t++) {
        // P1: layer0 MMA (reads cols 0..159)
        init_acc(acc, sBias, lane, wn);
        mma_slabs<5, 0>(acc, tid, lane, wm, wn, smem_base, sH, g, b, pfull, pempt);
        __syncthreads();
        // P2: epi0 (writes h0 cols 0..127) then layer1 h1-slabs (reads 160..287)
        epilogue(acc, lane, wm, wn, sH, sC0, 0);
        init_acc(acc, sBias + NG, lane, wn);
        mma_slabs<4, 160>(acc, tid, lane, wm, wn, smem_base, sH, g, b, pfull, pempt);
        __syncthreads();   // epi0 visible; all h1 reads done before epi1 rewrites
        // P3: layer1 h0-slabs; epi1 (writes 160..287); stage x(t+1) (writes 128..134)
        mma_slabs<4, 0>(acc, tid, lane, wm, wn, smem_base, sH, g, b, pfull, pempt);
        epilogue(acc, lane, wm, wn, sH, sC1, 160);
        if (t < 19) {
            for (int i = tid; i < MT * 7; i += NT) {
                int m = i / 7, k = i - m * 7;
                sH[m * LDA + 128 + k] = __float2half(target[(m0 + m) * 140 + (t + 1) * 7 + k]);
            }
        }
        __syncthreads();
    }

    // zero pred input for first decoder step (cols 130..134 hit zero weights)
    for (int i = tid; i < MT * 2; i += NT) {
        int m = i >> 1, k = i & 1;
        sH[m * LDA + 128 + k] = __float2half(0.0f);
    }
    __syncthreads();

    // ---- decoder: 25 steps ----
    for (int t = 0; t < 25; t++) {
        init_acc(acc, sBias + 2 * NG, lane, wn);
        mma_slabs<5, 0>(acc, tid, lane, wm, wn, smem_base, sH, g, b, pfull, pempt);
        __syncthreads();
        epilogue(acc, lane, wm, wn, sH, sC0, 0);
        init_acc(acc, sBias + 3 * NG, lane, wn);
        mma_slabs<4, 160>(acc, tid, lane, wm, wn, smem_base, sH, g, b, pfull, pempt);
        __syncthreads();
        mma_slabs<4, 0>(acc, tid, lane, wm, wn, smem_base, sH, g, b, pfull, pempt);
        epilogue(acc, lane, wm, wn, sH, sC1, 160);
        __syncthreads();   // h1 complete before projection

        // projection: pred = h1 @ outW^T + outb (16 warps x 4 rows)
#pragma unroll
        for (int r4 = 0; r4 < 4; r4++) {
            int mloc = warp * 4 + r4;
            float a0 = 0.0f, a1 = 0.0f;
#pragma unroll
            for (int j = 0; j < 4; j++) {
                int k = lane + 32 * j;
                float hv = __half2float(sH[mloc * LDA + 160 + k]);
                a0 += hv * sOW[k];
                a1 += hv * sOW[128 + k];
            }
#pragma unroll
            for (int off = 16; off > 0; off >>= 1) {
                a0 += __shfl_down_sync(0xffffffffu, a0, off);
                a1 += __shfl_down_sync(0xffffffffu, a1, off);
            }
            if (lane == 0) {
                a0 += sOB[0];
                a1 += sOB[1];
                long m = m0 + mloc;
                dout[m * 50 + t * 2 + 0] = a0;
                dout[m * 50 + t * 2 + 1] = a1;
                sH[mloc * LDA + 128] = __float2half(a0);
                sH[mloc * LDA + 129] = __float2half(a1);
            }
        }
        __syncthreads();   // pred visible to next layer0
    }

    if (tid == 0) {
#pragma unroll
        for (int i = 0; i < 3; i++) {
            mbar_inval(smem_base + SMO_MBF + i * 8);
            mbar_inval(smem_base + SMO_MBE + i * 8);
        }
    }
}

// ---------------- host ----------------
extern "C" void kernel_launch(void* const* d_in, const int* in_sizes, int n_in,
                              void* d_out, int out_size)
{
    const float* target = (const float*)d_in[0];
    const float* eWih0 = (const float*)d_in[4];
    const float* eWhh0 = (const float*)d_in[5];
    const float* ebih0 = (const float*)d_in[6];
    const float* ebhh0 = (const float*)d_in[7];
    const float* eWih1 = (const float*)d_in[8];
    const float* eWhh1 = (const float*)d_in[9];
    const float* ebih1 = (const float*)d_in[10];
    const float* ebhh1 = (const float*)d_in[11];
    const float* dWih0 = (const float*)d_in[12];
    const float* dWhh0 = (const float*)d_in[13];
    const float* dbih0 = (const float*)d_in[14];
    const float* dbhh0 = (const float*)d_in[15];
    const float* dWih1 = (const float*)d_in[16];
    const float* dWhh1 = (const float*)d_in[17];
    const float* dbih1 = (const float*)d_in[18];
    const float* dbhh1 = (const float*)d_in[19];
    const float* outW  = (const float*)d_in[20];
    const float* outb  = (const float*)d_in[21];
    float* out = (float*)d_out;

    cudaFuncSetAttribute(lstm_fused, cudaFuncAttributeMaxDynamicSharedMemorySize, SMEM_TOTAL);

    build_weights<<<26, NT>>>(eWih0, eWhh0, ebih0, ebhh0,
                              eWih1, eWhh1, ebih1, ebhh1,
                              dWih0, dWhh0, dbih0, dbhh0,
                              dWih1, dWhh1, dbih1, dbhh1);

    lstm_fused<<<BATCH / MT, NT, SMEM_TOTAL>>>(target, outW, outb, out);
}

// round 10
// speedup vs baseline: 4.1793x; 1.0320x over previous
#include <cuda_runtime.h>
#include <cuda_fp16.h>
#include <cstdint>

#define BATCH 65536
#define NG 512
#define MT 64
#define LDA 296          // sH leading dim (halves): conflict-free LDSM
#define LDC 132          // c leading dim (floats): conflict-free (4a+t map)
#define NT 512           // 16 warps
#define SLABH 16384      // halves per packed slab (512 x 32, SW64-swizzled)
#define SLABB 32768
#define TOTAL_SLABS 585  // 45 step-pairs x 13 slabs

// ---- packed swizzled weight slabs in gmem, in CONSUMPTION order ----
// per pair: [L0 ks0..4][L1 ks4..7][L1 ks0..3];  E-block pos 0..12, D-block pos 13..25
__device__ __align__(16) __half g_S[26 * SLABH];
__device__ float g_bias[4 * NG];

// ---- smem map (bytes) ----
#define SMO_H    0          // 64 x 296 fp16 (37888)
#define SMO_B    37888      // 3 x 32768 slab buffers (98304)
#define SMO_C0   136192     // 64 x 132 fp32 (33792)
#define SMO_C1   169984     // 64 x 132 fp32 (33792)
#define SMO_BIAS 203776     // 4 x 512 fp32 (8192)
#define SMO_OW   211968     // 256 fp32 (1024)
#define SMO_OB   212992     // 2 fp32
#define SMO_MBF  213000     // 3 full mbarriers
#define SMO_MBE  213024     // 3 empty mbarriers
#define SMEM_TOTAL 213048

// ---------------- helpers ----------------
__device__ __forceinline__ unsigned smem_u32(const void* p) {
    return (unsigned)__cvta_generic_to_shared(p);
}
__device__ __forceinline__ unsigned tanh2u(unsigned x) {
    unsigned y; asm("tanh.approx.f16x2 %0, %1;" : "=r"(y) : "r"(x)); return y;
}
__device__ __forceinline__ unsigned pack2(float a, float b) {
    __half2 h = __floats2half2_rn(a, b);
    return *reinterpret_cast<unsigned*>(&h);
}
__device__ __forceinline__ __half2 u2h(unsigned u) {
    return *reinterpret_cast<__half2*>(&u);
}
__device__ __forceinline__ void mbar_init(uint32_t a, uint32_t c) {
    asm volatile("mbarrier.init.shared.b64 [%0], %1;" :: "r"(a), "r"(c) : "memory");
}
__device__ __forceinline__ void mbar_inval(uint32_t a) {
    asm volatile("mbarrier.inval.shared.b64 [%0];" :: "r"(a) : "memory");
}
__device__ __forceinline__ void mbar_expect_tx(uint32_t a, uint32_t bytes) {
    asm volatile("mbarrier.arrive.expect_tx.shared.b64 _, [%0], %1;"
                 :: "r"(a), "r"(bytes) : "memory");
}
__device__ __forceinline__ void mbar_arrive(uint32_t a) {
    asm volatile("mbarrier.arrive.shared.b64 _, [%0];" :: "r"(a) : "memory");
}
__device__ __forceinline__ void mbar_wait(uint32_t mbar, int parity) {
    uint32_t done;
    asm volatile(
        "{\n\t.reg .pred p;\n\t"
        "mbarrier.try_wait.parity.acquire.cta.shared::cta.b64 p, [%1], %2;\n\t"
        "selp.b32 %0, 1, 0, p;\n\t}"
        : "=r"(done) : "r"(mbar), "r"((uint32_t)parity) : "memory");
    if (!done) {
        asm volatile(
            "{\n\t.reg .pred P1;\n\t"
            "WAIT_LOOP_%=:\n\t"
            "mbarrier.try_wait.parity.acquire.cta.shared::cta.b64 P1, [%0], %1, 0x989680;\n\t"
            "@P1 bra.uni WAIT_DONE_%=;\n\t"
            "bra.uni WAIT_LOOP_%=;\n\t"
            "WAIT_DONE_%=:\n\t}"
            :: "r"(mbar), "r"((uint32_t)parity) : "memory");
    }
}
__device__ __forceinline__ void bulk_g2s(uint32_t dst, const void* src,
                                         uint32_t bytes, uint32_t mbar) {
    asm volatile(
        "cp.async.bulk.shared::cta.global.mbarrier::complete_tx::bytes [%0], [%1], %2, [%3];"
        :: "r"(dst), "l"(src), "r"(bytes), "r"(mbar) : "memory");
}
__device__ __forceinline__ void ldsm4(unsigned addr, unsigned& r0, unsigned& r1,
                                      unsigned& r2, unsigned& r3) {
    asm volatile("ldmatrix.sync.aligned.m8n8.x4.shared.b16 {%0,%1,%2,%3}, [%4];"
                 : "=r"(r0), "=r"(r1), "=r"(r2), "=r"(r3) : "r"(addr));
}
__device__ __forceinline__ void mma16816(float* d, const unsigned* a, unsigned b0, unsigned b1) {
    asm volatile(
        "mma.sync.aligned.m16n8k16.row.col.f32.f16.f16.f32 "
        "{%0,%1,%2,%3},{%4,%5,%6,%7},{%8,%9},{%0,%1,%2,%3};"
        : "+f"(d[0]), "+f"(d[1]), "+f"(d[2]), "+f"(d[3])
        : "r"(a[0]), "r"(a[1]), "r"(a[2]), "r"(a[3]), "r"(b0), "r"(b1));
}
__device__ __forceinline__ const __half* slab_src(int gg) {
    int sp = gg / 13;
    int w  = gg - sp * 13;
    return g_S + (size_t)(((sp < 20) ? 0 : 13) + w) * SLABH;
}

// ---------------- prep: gate-interleave (shuffle-free map) + K-fold + SW64 + prescale ----
// Permuted gate-col: col(u,g) = (u>>2)*16*... decoded below. Gates i,f,o pre-scaled 0.5.
__global__ void build_weights(
    const float* __restrict__ eWih0, const float* __restrict__ eWhh0,
    const float* __restrict__ ebih0, const float* __restrict__ ebhh0,
    const float* __restrict__ eWih1, const float* __restrict__ eWhh1,
    const float* __restrict__ ebih1, const float* __restrict__ ebhh1,
    const float* __restrict__ dWih0, const float* __restrict__ dWhh0,
    const float* __restrict__ dbih0, const float* __restrict__ dbhh0,
    const float* __restrict__ dWih1, const float* __restrict__ dWhh1,
    const float* __restrict__ dbih1, const float* __restrict__ dbhh1)
{
    int sb = blockIdx.x;        // 0..25
    int phase, ks;
    if (sb < 5)       { phase = 0; ks = sb; }
    else if (sb < 13) { phase = 1; ks = sb - 5; }
    else if (sb < 18) { phase = 2; ks = sb - 13; }
    else              { phase = 3; ks = sb - 18; }

    int pos;
    if (phase == 0)      pos = ks;
    else if (phase == 1) pos = (ks >= 4) ? 5 + (ks - 4) : 9 + ks;
    else if (phase == 2) pos = 13 + ks;
    else                 pos = (ks >= 4) ? 18 + (ks - 4) : 22 + ks;
    char* dst = (char*)(g_S + (size_t)pos * SLABH);

    // decode permuted col np -> (unit h, gate g)
    int np = threadIdx.x;       // 0..511
    int wnn = np >> 6;
    int rem = np & 63;
    int q   = rem >> 4;
    int rem2 = rem & 15;
    int gg  = rem2 >> 3;        // gate high bit
    int t   = (rem2 & 7) >> 1;
    int e   = rem2 & 1;         // gate low bit
    int g   = gg * 2 + e;       // 0=i,1=f,2=g,3=o
    int h   = wnn * 16 + q * 4 + t;
    int src = g * 128 + h;
    float scale = (g == 2) ? 1.0f : 0.5f;   // sigmoid pre-scale for i,f,o

    for (int c = 0; c < 32; c++) {
        int kglob = ks * 32 + c;
        float v = 0.0f;
        if (phase == 0) {
            if (kglob < 128) v = eWhh0[src * 128 + kglob];
            else if (kglob < 135) v = eWih0[src * 7 + (kglob - 128)];
        } else if (phase == 1) {
            v = (kglob < 128) ? eWih1[src * 128 + kglob] : eWhh1[src * 128 + kglob - 128];
        } else if (phase == 2) {
            if (kglob < 128) v = dWhh0[src * 128 + kglob];
            else if (kglob < 130) v = dWih0[src * 2 + (kglob - 128)];
        } else {
            v = (kglob < 128) ? dWih1[src * 128 + kglob] : dWhh1[src * 128 + kglob - 128];
        }
        int off = np * 64 + c * 2;
        off ^= (off >> 3) & 0x30;     // SW64 swizzle
        *(__half*)(dst + off) = __float2half(v * scale);
    }
    if (ks == 0) {
        const float* bi = (phase == 0) ? ebih0 : (phase == 1) ? ebih1 : (phase == 2) ? dbih0 : dbih1;
        const float* bh = (phase == 0) ? ebhh0 : (phase == 1) ? ebhh1 : (phase == 2) ? dbhh0 : dbhh1;
        g_bias[phase * NG + np] = (bi[src] + bh[src]) * scale;
    }
}

// ---------------- acc init with bias ----------------
__device__ __forceinline__ void init_acc(float (&acc)[2][8][4], const float* bias,
                                         int lane, int wn)
{
#pragma unroll
    for (int ni = 0; ni < 8; ni++) {
        int c0 = wn * 64 + ni * 8 + 2 * (lane & 3);
        float b0 = bias[c0], b1 = bias[c0 + 1];
#pragma unroll
        for (int mi = 0; mi < 2; mi++) {
            acc[mi][ni][0] = b0; acc[mi][ni][1] = b1;
            acc[mi][ni][2] = b0; acc[mi][ni][3] = b1;
        }
    }
}

// ---------------- NSL slabs of MMA; A cols = ACOL0 + j*32 ----------------
template <int NSL, int ACOL0>
__device__ __forceinline__ void mma_slabs(
    float (&acc)[2][8][4], int tid, int lane, int wm, int wn, uint32_t smem_base,
    __half* sH, int& g, int& b, int& pfull, int& pempt)
{
    const uint32_t mbF = smem_base + SMO_MBF;
    const uint32_t mbE = smem_base + SMO_MBE;
#pragma unroll
    for (int j = 0; j < NSL; j++) {
        mbar_wait(mbF + b * 8, (pfull >> b) & 1);
        pfull ^= (1 << b);

        const int acol = ACOL0 + j * 32;
        const uint32_t bbase = smem_base + SMO_B + b * SLABB;

#pragma unroll
        for (int kf = 0; kf < 2; kf++) {
            unsigned a[2][4];
#pragma unroll
            for (int mi = 0; mi < 2; mi++) {
                unsigned addr = smem_u32(sH + (wm * 32 + mi * 16 + (lane & 15)) * LDA
                                            + acol + kf * 16 + (lane >> 4) * 8);
                ldsm4(addr, a[mi][0], a[mi][1], a[mi][2], a[mi][3]);
            }
#pragma unroll
            for (int nq = 0; nq < 4; nq++) {
                int nrow = wn * 64 + nq * 16 + (lane & 15);
                int off = nrow * 64 + (kf * 2 + (lane >> 4)) * 16;
                off ^= (off >> 3) & 0x30;
                unsigned b0, b1, b2, b3;
                ldsm4(bbase + off, b0, b1, b2, b3);
#pragma unroll
                for (int mi = 0; mi < 2; mi++) {
                    mma16816(acc[mi][2 * nq],     a[mi], b0, b2);
                    mma16816(acc[mi][2 * nq + 1], a[mi], b1, b3);
                }
            }
        }
        if (lane == 0) mbar_arrive(mbE + b * 8);

        bool more = (g + 3 < TOTAL_SLABS);
        if (tid == 0 && more) {
            mbar_wait(mbE + b * 8, (pempt >> b) & 1);
            mbar_expect_tx(mbF + b * 8, SLABB);
            bulk_g2s(smem_base + SMO_B + b * SLABB, slab_src(g + 3), SLABB, mbF + b * 8);
        }
        if (more) pempt ^= (1 << b);

        b = (b == 2) ? 0 : b + 1;
        g++;
    }
}

// ---------------- shuffle-free epilogue: compute (pre-sync) / store (post-sync) ----------
// acc[mi][2q] = (i,f) gates, acc[mi][2q+1] = (g,o) gates of unit wn*16+q*4+(lane&3),
// rows r0 = wm*32+mi*16+(lane>>2) and r0+8 in elements [0/1] vs [2/3].
__device__ __forceinline__ void epi_compute(
    float (&acc)[2][8][4], int lane, int wm, int wn,
    float* sC, unsigned (&hh)[8])
{
    const int t = lane & 3, a = lane >> 2;
    const __half2 h05 = __floats2half2_rn(0.5f, 0.5f);
#pragma unroll
    for (int mi = 0; mi < 2; mi++) {
        int r0 = wm * 32 + mi * 16 + a;
#pragma unroll
        for (int q = 0; q < 4; q++) {
            float* dA = acc[mi][2 * q];
            float* dB = acc[mi][2 * q + 1];
            __half2 si = __hfma2(u2h(tanh2u(pack2(dA[0], dA[2]))), h05, h05);
            __half2 sf = __hfma2(u2h(tanh2u(pack2(dA[1], dA[3]))), h05, h05);
            __half2 tg = u2h(tanh2u(pack2(dB[0], dB[2])));
            __half2 so = __hfma2(u2h(tanh2u(pack2(dB[1], dB[3]))), h05, h05);
            int hidx = wn * 16 + q * 4 + t;
            float2 fsi = __half22float2(si);
            float2 fsf = __half22float2(sf);
            float2 ftg = __half22float2(tg);
            float c0 = fsf.x * sC[r0 * LDC + hidx] + fsi.x * ftg.x;
            float c1 = fsf.y * sC[(r0 + 8) * LDC + hidx] + fsi.y * ftg.y;
            sC[r0 * LDC + hidx] = c0;
            sC[(r0 + 8) * LDC + hidx] = c1;
            __half2 hv = __hmul2(u2h(tanh2u(pack2(c0, c1))), so);
            hh[mi * 4 + q] = *reinterpret_cast<unsigned*>(&hv);
        }
    }
}
__device__ __forceinline__ void epi_store(
    const unsigned (&hh)[8], int lane, int wm, int wn, __half* sH, int hOff)
{
    const int t = lane & 3, a = lane >> 2;
#pragma unroll
    for (int mi = 0; mi < 2; mi++) {
        int r0 = wm * 32 + mi * 16 + a;
#pragma unroll
        for (int q = 0; q < 4; q++) {
            __half2 hv = u2h(hh[mi * 4 + q]);
            int hidx = wn * 16 + q * 4 + t;
            sH[r0 * LDA + hOff + hidx]       = __low2half(hv);
            sH[(r0 + 8) * LDA + hOff + hidx] = __high2half(hv);
        }
    }
}

// ---------------- the fused full-network kernel ----------------
__global__ __launch_bounds__(NT, 1)
void lstm_fused(const float* __restrict__ target,
                const float* __restrict__ outW, const float* __restrict__ outb,
                float* __restrict__ dout)
{
    extern __shared__ char smem[];
    uint32_t smem_base = smem_u32(smem);
    __half* sH    = (__half*)(smem + SMO_H);
    float*  sC0   = (float*)(smem + SMO_C0);
    float*  sC1   = (float*)(smem + SMO_C1);
    float*  sBias = (float*)(smem + SMO_BIAS);
    float*  sOW   = (float*)(smem + SMO_OW);
    float*  sOB   = (float*)(smem + SMO_OB);

    int tid  = threadIdx.x;
    int warp = tid >> 5, lane = tid & 31;
    int wm = warp >> 3, wn = warp & 7;
    long m0 = (long)blockIdx.x * MT;

    // ---- init ----
    if (tid == 0) {
#pragma unroll
        for (int i = 0; i < 3; i++) {
            mbar_init(smem_base + SMO_MBF + i * 8, 1);
            mbar_init(smem_base + SMO_MBE + i * 8, 16);
        }
    }
    for (int i = tid; i < MT * LDA; i += NT) sH[i] = __float2half(0.0f);
    for (int i = tid; i < MT * LDC; i += NT) { sC0[i] = 0.0f; sC1[i] = 0.0f; }
    for (int i = tid; i < 4 * NG; i += NT) sBias[i] = g_bias[i];
    if (tid < 256) sOW[tid] = outW[tid];
    if (tid < 2) sOB[tid] = outb[tid];
    for (int i = tid; i < MT * 7; i += NT) {    // stage x(0)
        int m = i / 7, k = i - m * 7;
        sH[m * LDA + 128 + k] = __float2half(target[(m0 + m) * 140 + k]);
    }
    __syncthreads();

    if (tid == 0) {
#pragma unroll
        for (int i = 0; i < 3; i++) {
            mbar_expect_tx(smem_base + SMO_MBF + i * 8, SLABB);
            bulk_g2s(smem_base + SMO_B + i * SLABB, slab_src(i), SLABB,
                     smem_base + SMO_MBF + i * 8);
        }
    }

    int g = 0, b = 0, pfull = 0, pempt = 0;
    float acc[2][8][4];
    unsigned hh[8];

    // ---- encoder: 20 steps ----
    for (int t = 0; t < 20; t++) {
        // P1: layer0 MMA (reads cols 0..159) + epi0 compute (c regs/smem only)
        init_acc(acc, sBias, lane, wn);
        mma_slabs<5, 0>(acc, tid, lane, wm, wn, smem_base, sH, g, b, pfull, pempt);
        epi_compute(acc, lane, wm, wn, sC0, hh);
        __syncthreads();
        // P2: epi0 store (h0, cols 0..127) + layer1 h1-slabs (read cols 160..287)
        epi_store(hh, lane, wm, wn, sH, 0);
        init_acc(acc, sBias + NG, lane, wn);
        mma_slabs<4, 160>(acc, tid, lane, wm, wn, smem_base, sH, g, b, pfull, pempt);
        __syncthreads();   // h1 reads done; epi0 stores visible
        // P3: layer1 h0-slabs (read 0..127) + epi1 compute/store (write 160..287) + stage-x
        mma_slabs<4, 0>(acc, tid, lane, wm, wn, smem_base, sH, g, b, pfull, pempt);
        epi_compute(acc, lane, wm, wn, sC1, hh);
        epi_store(hh, lane, wm, wn, sH, 160);   // safe: disjoint from cols 0..159 reads
        if (t < 19) {
            for (int i = tid; i < MT * 7; i += NT) {
                int m = i / 7, k = i - m * 7;
                sH[m * LDA + 128 + k] = __float2half(target[(m0 + m) * 140 + (t + 1) * 7 + k]);
            }
        }
        __syncthreads();
    }

    // zero pred input for first decoder step (cols 130..134 hit zero weights)
    for (int i = tid; i < MT * 2; i += NT) {
        int m = i >> 1, k = i & 1;
        sH[m * LDA + 128 + k] = __float2half(0.0f);
    }
    __syncthreads();

    // ---- decoder: 25 steps ----
    for (int t = 0; t < 25; t++) {
        init_acc(acc, sBias + 2 * NG, lane, wn);
        mma_slabs<5, 0>(acc, tid, lane, wm, wn, smem_base, sH, g, b, pfull, pempt);
        epi_compute(acc, lane, wm, wn, sC0, hh);
        __syncthreads();
        epi_store(hh, lane, wm, wn, sH, 0);
        init_acc(acc, sBias + 3 * NG, lane, wn);
        mma_slabs<4, 160>(acc, tid, lane, wm, wn, smem_base, sH, g, b, pfull, pempt);
        __syncthreads();
        mma_slabs<4, 0>(acc, tid, lane, wm, wn, smem_base, sH, g, b, pfull, pempt);
        epi_compute(acc, lane, wm, wn, sC1, hh);
        epi_store(hh, lane, wm, wn, sH, 160);
        __syncthreads();   // h1 complete before projection

        // projection: pred = h1 @ outW^T + outb (16 warps x 4 rows)
#pragma unroll
        for (int r4 = 0; r4 < 4; r4++) {
            int mloc = warp * 4 + r4;
            float a0 = 0.0f, a1 = 0.0f;
#pragma unroll
            for (int j = 0; j < 4; j++) {
                int k = lane + 32 * j;
                float hv = __half2float(sH[mloc * LDA + 160 + k]);
                a0 += hv * sOW[k];
                a1 += hv * sOW[128 + k];
            }
#pragma unroll
            for (int off = 16; off > 0; off >>= 1) {
                a0 += __shfl_down_sync(0xffffffffu, a0, off);
                a1 += __shfl_down_sync(0xffffffffu, a1, off);
            }
            if (lane == 0) {
                a0 += sOB[0];
                a1 += sOB[1];
                long m = m0 + mloc;
                dout[m * 50 + t * 2 + 0] = a0;
                dout[m * 50 + t * 2 + 1] = a1;
                sH[mloc * LDA + 128] = __float2half(a0);
                sH[mloc * LDA + 129] = __float2half(a1);
            }
        }
        __syncthreads();   // pred visible to next layer0
    }

    if (tid == 0) {
#pragma unroll
        for (int i = 0; i < 3; i++) {
            mbar_inval(smem_base + SMO_MBF + i * 8);
            mbar_inval(smem_base + SMO_MBE + i * 8);
        }
    }
}

// ---------------- host ----------------
extern "C" void kernel_launch(void* const* d_in, const int* in_sizes, int n_in,
                              void* d_out, int out_size)
{
    const float* target = (const float*)d_in[0];
    const float* eWih0 = (const float*)d_in[4];
    const float* eWhh0 = (const float*)d_in[5];
    const float* ebih0 = (const float*)d_in[6];
    const float* ebhh0 = (const float*)d_in[7];
    const float* eWih1 = (const float*)d_in[8];
    const float* eWhh1 = (const float*)d_in[9];
    const float* ebih1 = (const float*)d_in[10];
    const float* ebhh1 = (const float*)d_in[11];
    const float* dWih0 = (const float*)d_in[12];
    const float* dWhh0 = (const float*)d_in[13];
    const float* dbih0 = (const float*)d_in[14];
    const float* dbhh0 = (const float*)d_in[15];
    const float* dWih1 = (const float*)d_in[16];
    const float* dWhh1 = (const float*)d_in[17];
    const float* dbih1 = (const float*)d_in[18];
    const float* dbhh1 = (const float*)d_in[19];
    const float* outW  = (const float*)d_in[20];
    const float* outb  = (const float*)d_in[21];
    float* out = (float*)d_out;

    cudaFuncSetAttribute(lstm_fused, cudaFuncAttributeMaxDynamicSharedMemorySize, SMEM_TOTAL);

    build_weights<<<26, NT>>>(eWih0, eWhh0, ebih0, ebhh0,
                              eWih1, eWhh1, ebih1, ebhh1,
                              dWih0, dWhh0, dbih0, dbhh0,
                              dWih1, dWhh1, dbih1, dbhh1);

    lstm_fused<<<BATCH / MT, NT, SMEM_TOTAL>>>(target, outW, outb, out);
}